// round 8
// baseline (speedup 1.0000x reference)
#include <cuda_runtime.h>
#include <cuda_bf16.h>
#include <math_constants.h>
#include <cstdint>

#define B_  64
#define T_  1380
#define TP  1408        // T padded to multiple of 32
#define TP2 (TP/2)      // 704 packed pairs
#define T2  (T_/2)      // 690 real pairs
#define XD  96
#define XP2 (XD/2)      // 48
#define HD  192
#define HP2 (HD/2)      // 96
#define CN  345

// ---------------------------------------------------------------------------
// Scratch (device globals). hi/lo bf16 pairs packed in uint32 (low = lower k).
// ---------------------------------------------------------------------------
__device__ uint32_t g_W2h[(size_t)CN * TP2],      g_W2l[(size_t)CN * TP2];
__device__ uint32_t g_Xth[(size_t)B_ * XD * TP2], g_Xtl[(size_t)B_ * XD * TP2];
__device__ uint32_t g_W1th[(size_t)HD * XP2],     g_W1tl[(size_t)HD * XP2];
__device__ uint32_t g_Hh [(size_t)B_ * T_ * HP2], g_Hl [(size_t)B_ * T_ * HP2];
__device__ uint32_t g_Hth[(size_t)B_ * HD * TP2], g_Htl[(size_t)B_ * HD * TP2];
__device__ uint32_t g_Zh [(size_t)B_ * CN * XP2], g_Zl [(size_t)B_ * CN * XP2];
__device__ uint32_t g_Yh [(size_t)B_ * CN * HP2], g_Yl [(size_t)B_ * CN * HP2];
__device__ uint32_t g_Ph [(size_t)B_ * CN * TP2], g_Pl [(size_t)B_ * CN * TP2];
__device__ float    g_L  [(size_t)B_ * CN * T_];

// ---------------------------------------------------------------------------
// Helpers
// ---------------------------------------------------------------------------
__device__ __forceinline__ void split_pair(float x0, float x1,
                                           uint32_t& hi, uint32_t& lo) {
    __nv_bfloat16 h0 = __float2bfloat16_rn(x0);
    __nv_bfloat16 h1 = __float2bfloat16_rn(x1);
    float r0 = x0 - __bfloat162float(h0);
    float r1 = x1 - __bfloat162float(h1);
    __nv_bfloat16 l0 = __float2bfloat16_rn(r0);
    __nv_bfloat16 l1 = __float2bfloat16_rn(r1);
    hi = ((uint32_t)__bfloat16_as_ushort(h1) << 16) | __bfloat16_as_ushort(h0);
    lo = ((uint32_t)__bfloat16_as_ushort(l1) << 16) | __bfloat16_as_ushort(l0);
}

__device__ __forceinline__ void mma_bf16(float* c, const uint32_t* a, const uint32_t* b) {
    asm volatile(
        "mma.sync.aligned.m16n8k16.row.col.f32.bf16.bf16.f32 "
        "{%0,%1,%2,%3}, {%4,%5,%6,%7}, {%8,%9}, {%0,%1,%2,%3};"
        : "+f"(c[0]), "+f"(c[1]), "+f"(c[2]), "+f"(c[3])
        : "r"(a[0]), "r"(a[1]), "r"(a[2]), "r"(a[3]),
          "r"(b[0]), "r"(b[1]));
}

__device__ __forceinline__ void ldsm4(uint32_t* r, uint32_t saddr) {
    asm volatile("ldmatrix.sync.aligned.m8n8.x4.shared.b16 {%0,%1,%2,%3}, [%4];"
                 : "=r"(r[0]), "=r"(r[1]), "=r"(r[2]), "=r"(r[3]) : "r"(saddr));
}

__device__ __forceinline__ void cp16(uint32_t dst, const void* src, bool ok) {
    asm volatile(
        "{\n\t.reg .pred p;\n\t.reg .b32 sz;\n\t"
        "setp.ne.u32 p, %2, 0;\n\t"
        "selp.b32 sz, 16, 0, p;\n\t"
        "cp.async.cg.shared.global [%0], [%1], 16, sz;\n\t}"
        :: "r"(dst), "l"(src), "r"((uint32_t)ok) : "memory");
}
#define CP_COMMIT() asm volatile("cp.async.commit_group;" ::: "memory")

// ---------------------------------------------------------------------------
// Prepass: elementwise split+pack (zero-pad cols to Cp2 pairs)
// ---------------------------------------------------------------------------
__global__ void split_pack(const float* __restrict__ src,
                           uint32_t* __restrict__ dh, uint32_t* __restrict__ dl,
                           int rows, int C, int Cp2) {
    size_t idx = (size_t)blockIdx.x * 256 + threadIdx.x;
    size_t total = (size_t)rows * Cp2;
    if (idx >= total) return;
    int r = (int)(idx / Cp2);
    int j = (int)(idx - (size_t)r * Cp2);
    float2 v = make_float2(0.f, 0.f);
    if (2 * j < C)
        v = *reinterpret_cast<const float2*>(src + (size_t)r * C + 2 * j);
    uint32_t hi, lo;
    split_pair(v.x, v.y, hi, lo);
    dh[idx] = hi;
    dl[idx] = lo;
}

// ---------------------------------------------------------------------------
// Prepass: split + transpose + pack.  src [b][R][C] -> [b][C][Rp2]
// ---------------------------------------------------------------------------
__global__ void split_transpose(const float* __restrict__ src, size_t sSrc,
                                uint32_t* __restrict__ dh, uint32_t* __restrict__ dl,
                                size_t sDst, int R, int C, int Rp2) {
    __shared__ float t[32][33];
    const int b = blockIdx.z;
    src += sSrc * b;
    dh  += sDst * b;
    dl  += sDst * b;
    const int r0 = blockIdx.x * 32;
    const int c0 = blockIdx.y * 32;
    const int tx = threadIdx.x, ty = threadIdx.y;

    #pragma unroll
    for (int i = 0; i < 4; i++) {
        int r = r0 + ty + i * 8, c = c0 + tx;
        t[ty + i * 8][tx] = (r < R && c < C) ? src[(size_t)r * C + c] : 0.f;
    }
    __syncthreads();
    if (tx < 16) {
        #pragma unroll
        for (int i = 0; i < 4; i++) {
            int cc = ty + i * 8, c = c0 + cc;
            if (c < C) {
                uint32_t hi, lo;
                split_pair(t[2 * tx][cc], t[2 * tx + 1][cc], hi, lo);
                size_t o = (size_t)c * Rp2 + (r0 >> 1) + tx;
                dh[o] = hi;
                dl[o] = lo;
            }
        }
    }
}

// ---------------------------------------------------------------------------
// Fused H prepass: one read of H produces both packings.
//   g_Hh/g_Hl  : [b*T][HP2]   (pairs along HD)
//   g_Hth/g_Htl: [b][HD][TP2] (pairs along T, zero-padded to TP)
// Grid (TP/32, HD/32, B), block (32,8).
// ---------------------------------------------------------------------------
__global__ void prep_H(const float* __restrict__ H) {
    __shared__ float t[32][33];
    const int b = blockIdx.z;
    const float* src = H + (size_t)b * T_ * HD;
    const int r0 = blockIdx.x * 32;   // T dim
    const int c0 = blockIdx.y * 32;   // HD dim
    const int tx = threadIdx.x, ty = threadIdx.y;

    #pragma unroll
    for (int i = 0; i < 4; i++) {
        int r = r0 + ty + i * 8;
        t[ty + i * 8][tx] = (r < T_) ? src[(size_t)r * HD + c0 + tx] : 0.f;
    }
    __syncthreads();
    if (tx < 16) {
        // transposed pack (pairs along T)
        #pragma unroll
        for (int i = 0; i < 4; i++) {
            int cc = ty + i * 8, c = c0 + cc;
            uint32_t hi, lo;
            split_pair(t[2 * tx][cc], t[2 * tx + 1][cc], hi, lo);
            size_t o = ((size_t)b * HD + c) * TP2 + (r0 >> 1) + tx;
            g_Hth[o] = hi;
            g_Htl[o] = lo;
        }
        // direct pack (pairs along HD)
        #pragma unroll
        for (int i = 0; i < 4; i++) {
            int rr = ty + i * 8, r = r0 + rr;
            if (r < T_) {
                uint32_t hi, lo;
                split_pair(t[rr][2 * tx], t[rr][2 * tx + 1], hi, lo);
                size_t o = ((size_t)b * T_ + r) * HP2 + (c0 >> 1) + tx;
                g_Hh[o] = hi;
                g_Hl[o] = lo;
            }
        }
    }
}

// ---------------------------------------------------------------------------
// bf16 split-compensated tensor-core GEMM (NT, packed hi/lo operands).
//   C[b] = alpha * A[b] (M x Kp) @ B[b] (N x Kp)^T,  products hh+hl+lh
// BM=128, BN=128, BK=32, 512 threads (16 warps 4x4), warp tile 32x32.
// ldmatrix.x4 fragment loads; cp.async double-buffered.
// smem/stage: Ah[128][20] Al Bh[128][20] Bl  (u32; pitch 20 => LDSM-conflict-free)
// ---------------------------------------------------------------------------
template<bool OSPLIT>
__global__ __launch_bounds__(512, 1)
void gemm_bf16s(const uint32_t* __restrict__ Ah, const uint32_t* __restrict__ Al, size_t sA,
                const uint32_t* __restrict__ Bh, const uint32_t* __restrict__ Bl, size_t sB,
                float* __restrict__ Cf, uint32_t* __restrict__ Ch, uint32_t* __restrict__ Cl,
                size_t sC, int M, int N, int Kp, float alpha)
{
    constexpr int PITCH = 20;                 // u32 per row
    constexpr int OFF_AL = 2560, OFF_BH = 5120, OFF_BL = 7680;
    constexpr int STG = 10240;                // u32 per stage

    extern __shared__ uint32_t sm[];
    const uint32_t sbase = (uint32_t)__cvta_generic_to_shared(sm);

    const int b = blockIdx.z;
    Ah += sA * b;  Al += sA * b;
    Bh += sB * b;  Bl += sB * b;
    const int m0 = blockIdx.x * 128;
    const int n0 = blockIdx.y * 128;
    const int tid  = threadIdx.x;
    const int warp = tid >> 5, lane = tid & 31;
    const int wm = warp >> 2, wn = warp & 3;       // 4 x 4 warp grid
    const int l4 = lane >> 2, lk = lane & 3;
    const int Kp2 = Kp >> 1;

    // ldmatrix per-lane address components (bytes)
    const int lt = lane >> 3, lr = lane & 7;
    const uint32_t aoff = ((((lt & 1) * 8 + lr) * PITCH + (lt >> 1) * 4) << 2);
    const uint32_t boff = ((((lt >> 1) * 8 + lr) * PITCH + (lt & 1) * 4) << 2);

    float acc[2][4][4] = {};
    const int nck = Kp >> 5;

    // cp.async: each thread owns one 16B chunk per array (512 = 128 rows x 4)
    const int cr = tid >> 2, cc4 = tid & 3;
    const uint32_t dstA = sbase + ((cr * PITCH + cc4 * 4) << 2);

    auto load_tile = [&](int ck, int st) {
        const uint32_t stg = (uint32_t)(st * STG) << 2;
        const int k0 = ck * 16;
        {
            int gm = m0 + cr;
            bool ok = gm < M;
            const uint32_t* s1 = ok ? (Ah + (size_t)gm * Kp2 + k0 + cc4 * 4) : Ah;
            const uint32_t* s2 = ok ? (Al + (size_t)gm * Kp2 + k0 + cc4 * 4) : Al;
            cp16(dstA + stg, s1, ok);
            cp16(dstA + stg + (OFF_AL << 2), s2, ok);
        }
        {
            int gn = n0 + cr;
            bool ok = gn < N;
            const uint32_t* s1 = ok ? (Bh + (size_t)gn * Kp2 + k0 + cc4 * 4) : Bh;
            const uint32_t* s2 = ok ? (Bl + (size_t)gn * Kp2 + k0 + cc4 * 4) : Bl;
            cp16(dstA + stg + (OFF_BH << 2), s1, ok);
            cp16(dstA + stg + (OFF_BL << 2), s2, ok);
        }
    };

    load_tile(0, 0);
    CP_COMMIT();

    for (int ck = 0; ck < nck; ck++) {
        if (ck + 1 < nck) {
            load_tile(ck + 1, (ck + 1) & 1);
            CP_COMMIT();
            asm volatile("cp.async.wait_group 1;" ::: "memory");
        } else {
            asm volatile("cp.async.wait_group 0;" ::: "memory");
        }
        __syncthreads();

        const uint32_t stg = sbase + (((ck & 1) * STG) << 2);

        #pragma unroll
        for (int kk = 0; kk < 2; kk++) {
            const uint32_t kb = (uint32_t)(kk * 8) << 2;
            uint32_t a_h[2][4], a_l[2][4], b_h[4][2], b_l[4][2];
            #pragma unroll
            for (int mi = 0; mi < 2; mi++) {
                uint32_t base = stg + (((wm * 32 + mi * 16) * PITCH) << 2) + kb + aoff;
                ldsm4(a_h[mi], base);
                ldsm4(a_l[mi], base + (OFF_AL << 2));
            }
            #pragma unroll
            for (int pr = 0; pr < 2; pr++) {
                uint32_t base = stg + ((OFF_BH + (wn * 32 + pr * 16) * PITCH) << 2) + kb + boff;
                uint32_t bt[4];
                ldsm4(bt, base);
                b_h[2 * pr][0] = bt[0]; b_h[2 * pr][1] = bt[1];
                b_h[2 * pr + 1][0] = bt[2]; b_h[2 * pr + 1][1] = bt[3];
                ldsm4(bt, base + ((OFF_BL - OFF_BH) << 2));
                b_l[2 * pr][0] = bt[0]; b_l[2 * pr][1] = bt[1];
                b_l[2 * pr + 1][0] = bt[2]; b_l[2 * pr + 1][1] = bt[3];
            }
            #pragma unroll
            for (int mi = 0; mi < 2; mi++)
                #pragma unroll
                for (int ni = 0; ni < 4; ni++) {
                    mma_bf16(acc[mi][ni], a_h[mi], b_h[ni]);
                    mma_bf16(acc[mi][ni], a_h[mi], b_l[ni]);
                    mma_bf16(acc[mi][ni], a_l[mi], b_h[ni]);
                }
        }
        __syncthreads();
    }

    // ---- epilogue ----
    const int N2 = N >> 1;
    #pragma unroll
    for (int mi = 0; mi < 2; mi++) {
        #pragma unroll
        for (int ni = 0; ni < 4; ni++) {
            int r0 = m0 + wm * 32 + mi * 16 + l4;
            int c0 = n0 + wn * 32 + ni * 8 + 2 * lk;
            if (c0 < N) {
                if (OSPLIT) {
                    int pj = c0 >> 1;
                    if (r0 < M) {
                        uint32_t hi, lo;
                        split_pair(alpha * acc[mi][ni][0], alpha * acc[mi][ni][1], hi, lo);
                        Ch[sC * b + (size_t)r0 * N2 + pj] = hi;
                        Cl[sC * b + (size_t)r0 * N2 + pj] = lo;
                    }
                    if (r0 + 8 < M) {
                        uint32_t hi, lo;
                        split_pair(alpha * acc[mi][ni][2], alpha * acc[mi][ni][3], hi, lo);
                        Ch[sC * b + (size_t)(r0 + 8) * N2 + pj] = hi;
                        Cl[sC * b + (size_t)(r0 + 8) * N2 + pj] = lo;
                    }
                } else {
                    if (r0 < M) {
                        float2 v = make_float2(alpha * acc[mi][ni][0], alpha * acc[mi][ni][1]);
                        *reinterpret_cast<float2*>(Cf + sC * b + (size_t)r0 * N + c0) = v;
                    }
                    if (r0 + 8 < M) {
                        float2 v = make_float2(alpha * acc[mi][ni][2], alpha * acc[mi][ni][3]);
                        *reinterpret_cast<float2*>(Cf + sC * b + (size_t)(r0 + 8) * N + c0) = v;
                    }
                }
            }
        }
    }
}

// ---------------------------------------------------------------------------
// Softmax rows of g_L -> split-packed probs g_Ph/g_Pl (zero-padded).
// ---------------------------------------------------------------------------
__global__ void softmax_split() {
    const size_t row = (size_t)blockIdx.y * CN + blockIdx.x;
    const float* Lr = g_L + row * T_;
    const float4* p4 = reinterpret_cast<const float4*>(Lr);
    constexpr int N4 = T_ / 4;   // 345
    const int tid = threadIdx.x;
    const int lane = tid & 31, warp = tid >> 5;
    __shared__ float red[8];

    float m = -CUDART_INF_F;
    for (int i = tid; i < N4; i += 256) {
        float4 v = p4[i];
        m = fmaxf(m, fmaxf(fmaxf(v.x, v.y), fmaxf(v.z, v.w)));
    }
    #pragma unroll
    for (int o = 16; o > 0; o >>= 1) m = fmaxf(m, __shfl_xor_sync(0xffffffffu, m, o));
    if (lane == 0) red[warp] = m;
    __syncthreads();
    float M = red[0];
    #pragma unroll
    for (int j = 1; j < 8; j++) M = fmaxf(M, red[j]);
    __syncthreads();

    float s = 0.f;
    for (int i = tid; i < N4; i += 256) {
        float4 v = p4[i];
        s += __expf(v.x - M) + __expf(v.y - M) + __expf(v.z - M) + __expf(v.w - M);
    }
    #pragma unroll
    for (int o = 16; o > 0; o >>= 1) s += __shfl_xor_sync(0xffffffffu, s, o);
    if (lane == 0) red[warp] = s;
    __syncthreads();
    float S = red[0];
    #pragma unroll
    for (int j = 1; j < 8; j++) S += red[j];
    float inv = __frcp_rn(S);

    uint32_t* Ph = g_Ph + row * TP2;
    uint32_t* Pl = g_Pl + row * TP2;
    const float2* p2 = reinterpret_cast<const float2*>(Lr);
    for (int j = tid; j < TP2; j += 256) {
        uint32_t hi = 0, lo = 0;
        if (j < T2) {
            float2 v = p2[j];
            split_pair(__expf(v.x - M) * inv, __expf(v.y - M) * inv, hi, lo);
        }
        Ph[j] = hi;
        Pl[j] = lo;
    }
}

// ---------------------------------------------------------------------------

static inline int cdiv(int a, int b) { return (a + b - 1) / b; }

extern "C" void kernel_launch(void* const* d_in, const int* in_sizes, int n_in,
                              void* d_out, int out_size) {
    const float* X  = (const float*)d_in[0];  // [B,T,XD]
    const float* H  = (const float*)d_in[1];  // [B,T,HD]
    const float* W1 = (const float*)d_in[2];  // [XD,HD]
    const float* W2 = (const float*)d_in[3];  // [CN,T]
    float* out = (float*)d_out;               // [B,CN,HD]

    uint32_t *W2h, *W2l, *Xth, *Xtl, *W1th, *W1tl, *Hh, *Hl, *Hth, *Htl;
    uint32_t *Zh, *Zl, *Yh, *Yl, *Ph, *Pl;
    float* L;
    cudaGetSymbolAddress((void**)&W2h, g_W2h);  cudaGetSymbolAddress((void**)&W2l, g_W2l);
    cudaGetSymbolAddress((void**)&Xth, g_Xth);  cudaGetSymbolAddress((void**)&Xtl, g_Xtl);
    cudaGetSymbolAddress((void**)&W1th, g_W1th); cudaGetSymbolAddress((void**)&W1tl, g_W1tl);
    cudaGetSymbolAddress((void**)&Hh, g_Hh);    cudaGetSymbolAddress((void**)&Hl, g_Hl);
    cudaGetSymbolAddress((void**)&Hth, g_Hth);  cudaGetSymbolAddress((void**)&Htl, g_Htl);
    cudaGetSymbolAddress((void**)&Zh, g_Zh);    cudaGetSymbolAddress((void**)&Zl, g_Zl);
    cudaGetSymbolAddress((void**)&Yh, g_Yh);    cudaGetSymbolAddress((void**)&Yl, g_Yl);
    cudaGetSymbolAddress((void**)&Ph, g_Ph);    cudaGetSymbolAddress((void**)&Pl, g_Pl);
    cudaGetSymbolAddress((void**)&L,  g_L);

    const float scale = 1.0f / sqrtf((float)XD * (float)HD);

    constexpr int SMEM = 2 * 10240 * 4;   // 81920 B

    static bool attr_done = false;
    if (!attr_done) {
        cudaFuncSetAttribute(gemm_bf16s<true>,
            cudaFuncAttributeMaxDynamicSharedMemorySize, SMEM);
        cudaFuncSetAttribute(gemm_bf16s<false>,
            cudaFuncAttributeMaxDynamicSharedMemorySize, SMEM);
        attr_done = true;
    }

    // ---- prepass ----
    {
        size_t tot = (size_t)CN * TP2;
        split_pack<<<(int)cdiv((int)tot, 256), 256>>>(W2, W2h, W2l, CN, T_, TP2);
    }
    prep_H<<<dim3(TP / 32, HD / 32, B_), dim3(32, 8)>>>(H);
    split_transpose<<<dim3(TP / 32, cdiv(XD, 32), B_), dim3(32, 8)>>>(
        X, (size_t)T_ * XD, Xth, Xtl, (size_t)XD * TP2, T_, XD, TP2);
    split_transpose<<<dim3(XD / 32, cdiv(HD, 32), 1), dim3(32, 8)>>>(
        W1, 0, W1th, W1tl, 0, XD, HD, XP2);

    // 1) Z[b] = W2 @ X[b]       A=W2 [CN,TP], B=Xt [XD,TP] -> Z split [CN,XP2]
    gemm_bf16s<true><<<dim3(cdiv(CN, 128), cdiv(XD, 128), B_), 512, SMEM>>>(
        W2h, W2l, 0, Xth, Xtl, (size_t)XD * TP2,
        nullptr, Zh, Zl, (size_t)CN * XP2, CN, XD, TP, 1.0f);

    // 2) Y[b] = Z[b] @ W1       A=Z [CN,XD], B=W1t [HD,XD] -> Y split [CN,HP2]
    gemm_bf16s<true><<<dim3(cdiv(CN, 128), cdiv(HD, 128), B_), 512, SMEM>>>(
        Zh, Zl, (size_t)CN * XP2, W1th, W1tl, 0,
        nullptr, Yh, Yl, (size_t)CN * HP2, CN, HD, XD, 1.0f);

    // 3) L[b] = scale * Y[b] @ H[b]^T   A=Y [CN,HD], B=H [T,HD] -> L fp32
    gemm_bf16s<false><<<dim3(cdiv(CN, 128), cdiv(T_, 128), B_), 512, SMEM>>>(
        Yh, Yl, (size_t)CN * HP2, Hh, Hl, (size_t)T_ * HP2,
        L, nullptr, nullptr, (size_t)CN * T_, CN, T_, HD, scale);

    // 4) softmax rows of L -> P split [CN,TP2]
    softmax_split<<<dim3(CN, B_), 256>>>();

    // 5) out[b] = P[b] @ H[b]   A=P [CN,TP], B=Ht [HD,TP] -> out fp32
    gemm_bf16s<false><<<dim3(cdiv(CN, 128), cdiv(HD, 128), B_), 512, SMEM>>>(
        Ph, Pl, (size_t)CN * TP2, Hth, Htl, (size_t)HD * TP2,
        out, nullptr, nullptr, (size_t)CN * HD, CN, HD, TP, 1.0f);
}

// round 9
// speedup vs baseline: 1.1114x; 1.1114x over previous
#include <cuda_runtime.h>
#include <cuda_bf16.h>
#include <math_constants.h>
#include <cstdint>

#define B_  64
#define T_  1380
#define TP  1408        // T padded to multiple of 32
#define TP2 (TP/2)      // 704 packed pairs
#define T2  (T_/2)      // 690 real pairs
#define XD  96
#define XP2 (XD/2)      // 48
#define HD  192
#define HP2 (HD/2)      // 96
#define CN  345

// ---------------------------------------------------------------------------
// Scratch (device globals). hi/lo bf16 pairs packed in uint32 (low = lower k).
// ---------------------------------------------------------------------------
__device__ uint32_t g_W2h[(size_t)CN * TP2],      g_W2l[(size_t)CN * TP2];
__device__ uint32_t g_Xth[(size_t)B_ * XD * TP2], g_Xtl[(size_t)B_ * XD * TP2];
__device__ uint32_t g_W1th[(size_t)HD * XP2],     g_W1tl[(size_t)HD * XP2];
__device__ uint32_t g_Hh [(size_t)B_ * T_ * HP2], g_Hl [(size_t)B_ * T_ * HP2];
__device__ uint32_t g_Hth[(size_t)B_ * HD * TP2], g_Htl[(size_t)B_ * HD * TP2];
__device__ uint32_t g_Zh [(size_t)B_ * CN * XP2], g_Zl [(size_t)B_ * CN * XP2];
__device__ uint32_t g_Yh [(size_t)B_ * CN * HP2], g_Yl [(size_t)B_ * CN * HP2];
__device__ uint32_t g_Ph [(size_t)B_ * CN * TP2], g_Pl [(size_t)B_ * CN * TP2];
__device__ float    g_L  [(size_t)B_ * CN * T_];

// ---------------------------------------------------------------------------
// Helpers
// ---------------------------------------------------------------------------
__device__ __forceinline__ void split_pair(float x0, float x1,
                                           uint32_t& hi, uint32_t& lo) {
    __nv_bfloat16 h0 = __float2bfloat16_rn(x0);
    __nv_bfloat16 h1 = __float2bfloat16_rn(x1);
    float r0 = x0 - __bfloat162float(h0);
    float r1 = x1 - __bfloat162float(h1);
    __nv_bfloat16 l0 = __float2bfloat16_rn(r0);
    __nv_bfloat16 l1 = __float2bfloat16_rn(r1);
    hi = ((uint32_t)__bfloat16_as_ushort(h1) << 16) | __bfloat16_as_ushort(h0);
    lo = ((uint32_t)__bfloat16_as_ushort(l1) << 16) | __bfloat16_as_ushort(l0);
}

__device__ __forceinline__ void mma_bf16(float* c, const uint32_t* a, const uint32_t* b) {
    asm volatile(
        "mma.sync.aligned.m16n8k16.row.col.f32.bf16.bf16.f32 "
        "{%0,%1,%2,%3}, {%4,%5,%6,%7}, {%8,%9}, {%0,%1,%2,%3};"
        : "+f"(c[0]), "+f"(c[1]), "+f"(c[2]), "+f"(c[3])
        : "r"(a[0]), "r"(a[1]), "r"(a[2]), "r"(a[3]),
          "r"(b[0]), "r"(b[1]));
}

__device__ __forceinline__ void ldsm4(uint32_t* r, uint32_t saddr) {
    asm volatile("ldmatrix.sync.aligned.m8n8.x4.shared.b16 {%0,%1,%2,%3}, [%4];"
                 : "=r"(r[0]), "=r"(r[1]), "=r"(r[2]), "=r"(r[3]) : "r"(saddr));
}

__device__ __forceinline__ void cp16(uint32_t dst, const void* src, bool ok) {
    asm volatile(
        "{\n\t.reg .pred p;\n\t.reg .b32 sz;\n\t"
        "setp.ne.u32 p, %2, 0;\n\t"
        "selp.b32 sz, 16, 0, p;\n\t"
        "cp.async.cg.shared.global [%0], [%1], 16, sz;\n\t}"
        :: "r"(dst), "l"(src), "r"((uint32_t)ok) : "memory");
}
#define CP_COMMIT() asm volatile("cp.async.commit_group;" ::: "memory")

// ---------------------------------------------------------------------------
// Prepass: elementwise split+pack (zero-pad cols to Cp2 pairs)
// ---------------------------------------------------------------------------
__global__ void split_pack(const float* __restrict__ src,
                           uint32_t* __restrict__ dh, uint32_t* __restrict__ dl,
                           int rows, int C, int Cp2) {
    size_t idx = (size_t)blockIdx.x * 256 + threadIdx.x;
    size_t total = (size_t)rows * Cp2;
    if (idx >= total) return;
    int r = (int)(idx / Cp2);
    int j = (int)(idx - (size_t)r * Cp2);
    float2 v = make_float2(0.f, 0.f);
    if (2 * j < C)
        v = *reinterpret_cast<const float2*>(src + (size_t)r * C + 2 * j);
    uint32_t hi, lo;
    split_pair(v.x, v.y, hi, lo);
    dh[idx] = hi;
    dl[idx] = lo;
}

// ---------------------------------------------------------------------------
// Prepass: split + transpose + pack.  src [b][R][C] -> [b][C][Rp2]
// ---------------------------------------------------------------------------
__global__ void split_transpose(const float* __restrict__ src, size_t sSrc,
                                uint32_t* __restrict__ dh, uint32_t* __restrict__ dl,
                                size_t sDst, int R, int C, int Rp2) {
    __shared__ float t[32][33];
    const int b = blockIdx.z;
    src += sSrc * b;
    dh  += sDst * b;
    dl  += sDst * b;
    const int r0 = blockIdx.x * 32;
    const int c0 = blockIdx.y * 32;
    const int tx = threadIdx.x, ty = threadIdx.y;

    #pragma unroll
    for (int i = 0; i < 4; i++) {
        int r = r0 + ty + i * 8, c = c0 + tx;
        t[ty + i * 8][tx] = (r < R && c < C) ? src[(size_t)r * C + c] : 0.f;
    }
    __syncthreads();
    if (tx < 16) {
        #pragma unroll
        for (int i = 0; i < 4; i++) {
            int cc = ty + i * 8, c = c0 + cc;
            if (c < C) {
                uint32_t hi, lo;
                split_pair(t[2 * tx][cc], t[2 * tx + 1][cc], hi, lo);
                size_t o = (size_t)c * Rp2 + (r0 >> 1) + tx;
                dh[o] = hi;
                dl[o] = lo;
            }
        }
    }
}

// ---------------------------------------------------------------------------
// Fused H prepass: one read of H produces both packings.
//   g_Hh/g_Hl  : [b*T][HP2]   (pairs along HD)
//   g_Hth/g_Htl: [b][HD][TP2] (pairs along T, zero-padded to TP)
// Grid (TP/32, HD/32, B), block (32,8).
// ---------------------------------------------------------------------------
__global__ void prep_H(const float* __restrict__ H) {
    __shared__ float t[32][33];
    const int b = blockIdx.z;
    const float* src = H + (size_t)b * T_ * HD;
    const int r0 = blockIdx.x * 32;   // T dim
    const int c0 = blockIdx.y * 32;   // HD dim
    const int tx = threadIdx.x, ty = threadIdx.y;

    #pragma unroll
    for (int i = 0; i < 4; i++) {
        int r = r0 + ty + i * 8;
        t[ty + i * 8][tx] = (r < T_) ? src[(size_t)r * HD + c0 + tx] : 0.f;
    }
    __syncthreads();
    if (tx < 16) {
        // transposed pack (pairs along T)
        #pragma unroll
        for (int i = 0; i < 4; i++) {
            int cc = ty + i * 8, c = c0 + cc;
            uint32_t hi, lo;
            split_pair(t[2 * tx][cc], t[2 * tx + 1][cc], hi, lo);
            size_t o = ((size_t)b * HD + c) * TP2 + (r0 >> 1) + tx;
            g_Hth[o] = hi;
            g_Htl[o] = lo;
        }
        // direct pack (pairs along HD)
        #pragma unroll
        for (int i = 0; i < 4; i++) {
            int rr = ty + i * 8, r = r0 + rr;
            if (r < T_) {
                uint32_t hi, lo;
                split_pair(t[rr][2 * tx], t[rr][2 * tx + 1], hi, lo);
                size_t o = ((size_t)b * T_ + r) * HP2 + (c0 >> 1) + tx;
                g_Hh[o] = hi;
                g_Hl[o] = lo;
            }
        }
    }
}

// ---------------------------------------------------------------------------
// bf16 split-compensated tensor-core GEMM (NT, packed hi/lo operands).
//   C[b] = alpha * A[b] (M x Kp) @ B[b] (N x Kp)^T,  products hh+hl+lh
// BM=128, BN=128, BK=32, 256 threads (8 warps, 4x2), warp tile 32x64.
// ldmatrix.x4 fragment loads; cp.async double-buffered.
// smem/stage: Ah[128][20] Al Bh[128][20] Bl (u32). 2 CTAs/SM via lb(256,2).
// ---------------------------------------------------------------------------
template<bool OSPLIT>
__global__ __launch_bounds__(256, 2)
void gemm_bf16s(const uint32_t* __restrict__ Ah, const uint32_t* __restrict__ Al, size_t sA,
                const uint32_t* __restrict__ Bh, const uint32_t* __restrict__ Bl, size_t sB,
                float* __restrict__ Cf, uint32_t* __restrict__ Ch, uint32_t* __restrict__ Cl,
                size_t sC, int M, int N, int Kp, float alpha)
{
    constexpr int PITCH = 20;                 // u32 per row
    constexpr int OFF_AL = 2560, OFF_BH = 5120, OFF_BL = 7680;
    constexpr int STG = 10240;                // u32 per stage

    extern __shared__ uint32_t sm[];
    const uint32_t sbase = (uint32_t)__cvta_generic_to_shared(sm);

    const int b = blockIdx.z;
    Ah += sA * b;  Al += sA * b;
    Bh += sB * b;  Bl += sB * b;
    const int m0 = blockIdx.x * 128;
    const int n0 = blockIdx.y * 128;
    const int tid  = threadIdx.x;
    const int warp = tid >> 5, lane = tid & 31;
    const int wm = warp >> 1, wn = warp & 1;       // 4 x 2 warp grid
    const int l4 = lane >> 2, lk = lane & 3;
    const int Kp2 = Kp >> 1;

    // ldmatrix per-lane address components (bytes)
    const int lt = lane >> 3, lr = lane & 7;
    const uint32_t aoff = ((((lt & 1) * 8 + lr) * PITCH + (lt >> 1) * 4) << 2);
    const uint32_t boff = ((((lt >> 1) * 8 + lr) * PITCH + (lt & 1) * 4) << 2);

    float acc[2][8][4] = {};
    const int nck = Kp >> 5;

    auto load_tile = [&](int ck, int st) {
        const uint32_t stg = (uint32_t)(st * STG) << 2;
        const int k0 = ck * 16;
        // A: 1024 chunks (2 arrays x 128 rows x 4)
        #pragma unroll
        for (int i = 0; i < 4; i++) {
            int idx = tid + i * 256;
            int arr = idx >> 9, rem = idx & 511;
            int r = rem >> 2, c4 = rem & 3;
            int gm = m0 + r;
            bool ok = gm < M;
            const uint32_t* base = arr ? Al : Ah;
            const uint32_t* src = ok ? (base + (size_t)gm * Kp2 + k0 + c4 * 4) : base;
            cp16(sbase + stg + ((arr * OFF_AL + r * PITCH + c4 * 4) << 2), src, ok);
        }
        // B: 1024 chunks
        #pragma unroll
        for (int i = 0; i < 4; i++) {
            int idx = tid + i * 256;
            int arr = idx >> 9, rem = idx & 511;
            int r = rem >> 2, c4 = rem & 3;
            int gn = n0 + r;
            bool ok = gn < N;
            const uint32_t* base = arr ? Bl : Bh;
            const uint32_t* src = ok ? (base + (size_t)gn * Kp2 + k0 + c4 * 4) : base;
            cp16(sbase + stg + ((OFF_BH + arr * (OFF_BL - OFF_BH) + r * PITCH + c4 * 4) << 2),
                 src, ok);
        }
    };

    load_tile(0, 0);
    CP_COMMIT();

    for (int ck = 0; ck < nck; ck++) {
        if (ck + 1 < nck) {
            load_tile(ck + 1, (ck + 1) & 1);
            CP_COMMIT();
            asm volatile("cp.async.wait_group 1;" ::: "memory");
        } else {
            asm volatile("cp.async.wait_group 0;" ::: "memory");
        }
        __syncthreads();

        const uint32_t stg = sbase + (((ck & 1) * STG) << 2);

        #pragma unroll
        for (int kk = 0; kk < 2; kk++) {
            const uint32_t kb = (uint32_t)(kk * 8) << 2;
            uint32_t a_h[2][4], a_l[2][4], b_h[8][2], b_l[8][2];
            #pragma unroll
            for (int mi = 0; mi < 2; mi++) {
                uint32_t base = stg + (((wm * 32 + mi * 16) * PITCH) << 2) + kb + aoff;
                ldsm4(a_h[mi], base);
                ldsm4(a_l[mi], base + (OFF_AL << 2));
            }
            #pragma unroll
            for (int pr = 0; pr < 4; pr++) {
                uint32_t base = stg + ((OFF_BH + (wn * 64 + pr * 16) * PITCH) << 2) + kb + boff;
                uint32_t bt[4];
                ldsm4(bt, base);
                b_h[2 * pr][0] = bt[0]; b_h[2 * pr][1] = bt[1];
                b_h[2 * pr + 1][0] = bt[2]; b_h[2 * pr + 1][1] = bt[3];
                ldsm4(bt, base + ((OFF_BL - OFF_BH) << 2));
                b_l[2 * pr][0] = bt[0]; b_l[2 * pr][1] = bt[1];
                b_l[2 * pr + 1][0] = bt[2]; b_l[2 * pr + 1][1] = bt[3];
            }
            #pragma unroll
            for (int mi = 0; mi < 2; mi++)
                #pragma unroll
                for (int ni = 0; ni < 8; ni++) {
                    mma_bf16(acc[mi][ni], a_h[mi], b_h[ni]);
                    mma_bf16(acc[mi][ni], a_h[mi], b_l[ni]);
                    mma_bf16(acc[mi][ni], a_l[mi], b_h[ni]);
                }
        }
        __syncthreads();
    }

    // ---- epilogue ----
    const int N2 = N >> 1;
    #pragma unroll
    for (int mi = 0; mi < 2; mi++) {
        #pragma unroll
        for (int ni = 0; ni < 8; ni++) {
            int r0 = m0 + wm * 32 + mi * 16 + l4;
            int c0 = n0 + wn * 64 + ni * 8 + 2 * lk;
            if (c0 < N) {
                if (OSPLIT) {
                    int pj = c0 >> 1;
                    if (r0 < M) {
                        uint32_t hi, lo;
                        split_pair(alpha * acc[mi][ni][0], alpha * acc[mi][ni][1], hi, lo);
                        Ch[sC * b + (size_t)r0 * N2 + pj] = hi;
                        Cl[sC * b + (size_t)r0 * N2 + pj] = lo;
                    }
                    if (r0 + 8 < M) {
                        uint32_t hi, lo;
                        split_pair(alpha * acc[mi][ni][2], alpha * acc[mi][ni][3], hi, lo);
                        Ch[sC * b + (size_t)(r0 + 8) * N2 + pj] = hi;
                        Cl[sC * b + (size_t)(r0 + 8) * N2 + pj] = lo;
                    }
                } else {
                    if (r0 < M) {
                        float2 v = make_float2(alpha * acc[mi][ni][0], alpha * acc[mi][ni][1]);
                        *reinterpret_cast<float2*>(Cf + sC * b + (size_t)r0 * N + c0) = v;
                    }
                    if (r0 + 8 < M) {
                        float2 v = make_float2(alpha * acc[mi][ni][2], alpha * acc[mi][ni][3]);
                        *reinterpret_cast<float2*>(Cf + sC * b + (size_t)(r0 + 8) * N + c0) = v;
                    }
                }
            }
        }
    }
}

// ---------------------------------------------------------------------------
// Softmax rows of g_L -> split-packed probs g_Ph/g_Pl (zero-padded).
// ---------------------------------------------------------------------------
__global__ void softmax_split() {
    const size_t row = (size_t)blockIdx.y * CN + blockIdx.x;
    const float* Lr = g_L + row * T_;
    const float4* p4 = reinterpret_cast<const float4*>(Lr);
    constexpr int N4 = T_ / 4;   // 345
    const int tid = threadIdx.x;
    const int lane = tid & 31, warp = tid >> 5;
    __shared__ float red[8];

    float m = -CUDART_INF_F;
    for (int i = tid; i < N4; i += 256) {
        float4 v = p4[i];
        m = fmaxf(m, fmaxf(fmaxf(v.x, v.y), fmaxf(v.z, v.w)));
    }
    #pragma unroll
    for (int o = 16; o > 0; o >>= 1) m = fmaxf(m, __shfl_xor_sync(0xffffffffu, m, o));
    if (lane == 0) red[warp] = m;
    __syncthreads();
    float M = red[0];
    #pragma unroll
    for (int j = 1; j < 8; j++) M = fmaxf(M, red[j]);
    __syncthreads();

    float s = 0.f;
    for (int i = tid; i < N4; i += 256) {
        float4 v = p4[i];
        s += __expf(v.x - M) + __expf(v.y - M) + __expf(v.z - M) + __expf(v.w - M);
    }
    #pragma unroll
    for (int o = 16; o > 0; o >>= 1) s += __shfl_xor_sync(0xffffffffu, s, o);
    if (lane == 0) red[warp] = s;
    __syncthreads();
    float S = red[0];
    #pragma unroll
    for (int j = 1; j < 8; j++) S += red[j];
    float inv = __frcp_rn(S);

    uint32_t* Ph = g_Ph + row * TP2;
    uint32_t* Pl = g_Pl + row * TP2;
    const float2* p2 = reinterpret_cast<const float2*>(Lr);
    for (int j = tid; j < TP2; j += 256) {
        uint32_t hi = 0, lo = 0;
        if (j < T2) {
            float2 v = p2[j];
            split_pair(__expf(v.x - M) * inv, __expf(v.y - M) * inv, hi, lo);
        }
        Ph[j] = hi;
        Pl[j] = lo;
    }
}

// ---------------------------------------------------------------------------

static inline int cdiv(int a, int b) { return (a + b - 1) / b; }

extern "C" void kernel_launch(void* const* d_in, const int* in_sizes, int n_in,
                              void* d_out, int out_size) {
    const float* X  = (const float*)d_in[0];  // [B,T,XD]
    const float* H  = (const float*)d_in[1];  // [B,T,HD]
    const float* W1 = (const float*)d_in[2];  // [XD,HD]
    const float* W2 = (const float*)d_in[3];  // [CN,T]
    float* out = (float*)d_out;               // [B,CN,HD]

    uint32_t *W2h, *W2l, *Xth, *Xtl, *W1th, *W1tl, *Hh, *Hl, *Hth, *Htl;
    uint32_t *Zh, *Zl, *Yh, *Yl, *Ph, *Pl;
    float* L;
    cudaGetSymbolAddress((void**)&W2h, g_W2h);  cudaGetSymbolAddress((void**)&W2l, g_W2l);
    cudaGetSymbolAddress((void**)&Xth, g_Xth);  cudaGetSymbolAddress((void**)&Xtl, g_Xtl);
    cudaGetSymbolAddress((void**)&W1th, g_W1th); cudaGetSymbolAddress((void**)&W1tl, g_W1tl);
    cudaGetSymbolAddress((void**)&Hh, g_Hh);    cudaGetSymbolAddress((void**)&Hl, g_Hl);
    cudaGetSymbolAddress((void**)&Hth, g_Hth);  cudaGetSymbolAddress((void**)&Htl, g_Htl);
    cudaGetSymbolAddress((void**)&Zh, g_Zh);    cudaGetSymbolAddress((void**)&Zl, g_Zl);
    cudaGetSymbolAddress((void**)&Yh, g_Yh);    cudaGetSymbolAddress((void**)&Yl, g_Yl);
    cudaGetSymbolAddress((void**)&Ph, g_Ph);    cudaGetSymbolAddress((void**)&Pl, g_Pl);
    cudaGetSymbolAddress((void**)&L,  g_L);

    const float scale = 1.0f / sqrtf((float)XD * (float)HD);

    constexpr int SMEM = 2 * 10240 * 4;   // 81920 B

    static bool attr_done = false;
    if (!attr_done) {
        cudaFuncSetAttribute(gemm_bf16s<true>,
            cudaFuncAttributeMaxDynamicSharedMemorySize, SMEM);
        cudaFuncSetAttribute(gemm_bf16s<false>,
            cudaFuncAttributeMaxDynamicSharedMemorySize, SMEM);
        attr_done = true;
    }

    // ---- prepass ----
    {
        size_t tot = (size_t)CN * TP2;
        split_pack<<<(int)cdiv((int)tot, 256), 256>>>(W2, W2h, W2l, CN, T_, TP2);
    }
    prep_H<<<dim3(TP / 32, HD / 32, B_), dim3(32, 8)>>>(H);
    split_transpose<<<dim3(TP / 32, cdiv(XD, 32), B_), dim3(32, 8)>>>(
        X, (size_t)T_ * XD, Xth, Xtl, (size_t)XD * TP2, T_, XD, TP2);
    split_transpose<<<dim3(XD / 32, cdiv(HD, 32), 1), dim3(32, 8)>>>(
        W1, 0, W1th, W1tl, 0, XD, HD, XP2);

    // 1) Z[b] = W2 @ X[b]       A=W2 [CN,TP], B=Xt [XD,TP] -> Z split [CN,XP2]
    gemm_bf16s<true><<<dim3(cdiv(CN, 128), cdiv(XD, 128), B_), 256, SMEM>>>(
        W2h, W2l, 0, Xth, Xtl, (size_t)XD * TP2,
        nullptr, Zh, Zl, (size_t)CN * XP2, CN, XD, TP, 1.0f);

    // 2) Y[b] = Z[b] @ W1       A=Z [CN,XD], B=W1t [HD,XD] -> Y split [CN,HP2]
    gemm_bf16s<true><<<dim3(cdiv(CN, 128), cdiv(HD, 128), B_), 256, SMEM>>>(
        Zh, Zl, (size_t)CN * XP2, W1th, W1tl, 0,
        nullptr, Yh, Yl, (size_t)CN * HP2, CN, HD, XD, 1.0f);

    // 3) L[b] = scale * Y[b] @ H[b]^T   A=Y [CN,HD], B=H [T,HD] -> L fp32
    gemm_bf16s<false><<<dim3(cdiv(CN, 128), cdiv(T_, 128), B_), 256, SMEM>>>(
        Yh, Yl, (size_t)CN * HP2, Hh, Hl, (size_t)T_ * HP2,
        L, nullptr, nullptr, (size_t)CN * T_, CN, T_, HD, scale);

    // 4) softmax rows of L -> P split [CN,TP2]
    softmax_split<<<dim3(CN, B_), 256>>>();

    // 5) out[b] = P[b] @ H[b]   A=P [CN,TP], B=Ht [HD,TP] -> out fp32
    gemm_bf16s<false><<<dim3(cdiv(CN, 128), cdiv(HD, 128), B_), 256, SMEM>>>(
        Ph, Pl, (size_t)CN * TP2, Hth, Htl, (size_t)HD * TP2,
        out, nullptr, nullptr, (size_t)CN * HD, CN, HD, TP, 1.0f);
}

// round 10
// speedup vs baseline: 1.4299x; 1.2866x over previous
#include <cuda_runtime.h>
#include <cuda_bf16.h>
#include <math_constants.h>
#include <cstdint>

#define B_  64
#define T_  1380
#define TP  1408        // T padded to multiple of 32
#define TP2 (TP/2)      // 704 packed pairs
#define T2  (T_/2)      // 690 real pairs
#define XD  96
#define XP2 (XD/2)      // 48
#define HD  192
#define HP2 (HD/2)      // 96
#define CN  345

// ---------------------------------------------------------------------------
// Scratch (device globals). hi/lo bf16 pairs packed in uint32 (low = lower k).
// ---------------------------------------------------------------------------
__device__ uint32_t g_W2h[(size_t)CN * TP2],      g_W2l[(size_t)CN * TP2];
__device__ uint32_t g_Xth[(size_t)B_ * XD * TP2], g_Xtl[(size_t)B_ * XD * TP2];
__device__ uint32_t g_W1th[(size_t)HD * XP2],     g_W1tl[(size_t)HD * XP2];
__device__ uint32_t g_Hh [(size_t)B_ * T_ * HP2], g_Hl [(size_t)B_ * T_ * HP2];
__device__ uint32_t g_Hth[(size_t)B_ * HD * TP2], g_Htl[(size_t)B_ * HD * TP2];
__device__ uint32_t g_Zh [(size_t)B_ * CN * XP2], g_Zl [(size_t)B_ * CN * XP2];
__device__ uint32_t g_Yh [(size_t)B_ * CN * HP2], g_Yl [(size_t)B_ * CN * HP2];
__device__ uint32_t g_Ph [(size_t)B_ * CN * TP2], g_Pl [(size_t)B_ * CN * TP2];
__device__ float    g_L  [(size_t)B_ * CN * T_];

// ---------------------------------------------------------------------------
// Helpers
// ---------------------------------------------------------------------------
__device__ __forceinline__ void split_pair(float x0, float x1,
                                           uint32_t& hi, uint32_t& lo) {
    __nv_bfloat16 h0 = __float2bfloat16_rn(x0);
    __nv_bfloat16 h1 = __float2bfloat16_rn(x1);
    float r0 = x0 - __bfloat162float(h0);
    float r1 = x1 - __bfloat162float(h1);
    __nv_bfloat16 l0 = __float2bfloat16_rn(r0);
    __nv_bfloat16 l1 = __float2bfloat16_rn(r1);
    hi = ((uint32_t)__bfloat16_as_ushort(h1) << 16) | __bfloat16_as_ushort(h0);
    lo = ((uint32_t)__bfloat16_as_ushort(l1) << 16) | __bfloat16_as_ushort(l0);
}

__device__ __forceinline__ void mma_bf16(float* c, const uint32_t* a, const uint32_t* b) {
    asm volatile(
        "mma.sync.aligned.m16n8k16.row.col.f32.bf16.bf16.f32 "
        "{%0,%1,%2,%3}, {%4,%5,%6,%7}, {%8,%9}, {%0,%1,%2,%3};"
        : "+f"(c[0]), "+f"(c[1]), "+f"(c[2]), "+f"(c[3])
        : "r"(a[0]), "r"(a[1]), "r"(a[2]), "r"(a[3]),
          "r"(b[0]), "r"(b[1]));
}

__device__ __forceinline__ void ldsm4(uint32_t* r, uint32_t saddr) {
    asm volatile("ldmatrix.sync.aligned.m8n8.x4.shared.b16 {%0,%1,%2,%3}, [%4];"
                 : "=r"(r[0]), "=r"(r[1]), "=r"(r[2]), "=r"(r[3]) : "r"(saddr));
}

__device__ __forceinline__ void cp16(uint32_t dst, const void* src, bool ok) {
    asm volatile(
        "{\n\t.reg .pred p;\n\t.reg .b32 sz;\n\t"
        "setp.ne.u32 p, %2, 0;\n\t"
        "selp.b32 sz, 16, 0, p;\n\t"
        "cp.async.cg.shared.global [%0], [%1], 16, sz;\n\t}"
        :: "r"(dst), "l"(src), "r"((uint32_t)ok) : "memory");
}
#define CP_COMMIT() asm volatile("cp.async.commit_group;" ::: "memory")

// ---------------------------------------------------------------------------
// Prepass: elementwise split+pack (zero-pad cols to Cp2 pairs)
// ---------------------------------------------------------------------------
__global__ void split_pack(const float* __restrict__ src,
                           uint32_t* __restrict__ dh, uint32_t* __restrict__ dl,
                           int rows, int C, int Cp2) {
    size_t idx = (size_t)blockIdx.x * 256 + threadIdx.x;
    size_t total = (size_t)rows * Cp2;
    if (idx >= total) return;
    int r = (int)(idx / Cp2);
    int j = (int)(idx - (size_t)r * Cp2);
    float2 v = make_float2(0.f, 0.f);
    if (2 * j < C)
        v = *reinterpret_cast<const float2*>(src + (size_t)r * C + 2 * j);
    uint32_t hi, lo;
    split_pair(v.x, v.y, hi, lo);
    dh[idx] = hi;
    dl[idx] = lo;
}

// ---------------------------------------------------------------------------
// Prepass: split + transpose + pack.  src [b][R][C] -> [b][C][Rp2]
// ---------------------------------------------------------------------------
__global__ void split_transpose(const float* __restrict__ src, size_t sSrc,
                                uint32_t* __restrict__ dh, uint32_t* __restrict__ dl,
                                size_t sDst, int R, int C, int Rp2) {
    __shared__ float t[32][33];
    const int b = blockIdx.z;
    src += sSrc * b;
    dh  += sDst * b;
    dl  += sDst * b;
    const int r0 = blockIdx.x * 32;
    const int c0 = blockIdx.y * 32;
    const int tx = threadIdx.x, ty = threadIdx.y;

    #pragma unroll
    for (int i = 0; i < 4; i++) {
        int r = r0 + ty + i * 8, c = c0 + tx;
        t[ty + i * 8][tx] = (r < R && c < C) ? src[(size_t)r * C + c] : 0.f;
    }
    __syncthreads();
    if (tx < 16) {
        #pragma unroll
        for (int i = 0; i < 4; i++) {
            int cc = ty + i * 8, c = c0 + cc;
            if (c < C) {
                uint32_t hi, lo;
                split_pair(t[2 * tx][cc], t[2 * tx + 1][cc], hi, lo);
                size_t o = (size_t)c * Rp2 + (r0 >> 1) + tx;
                dh[o] = hi;
                dl[o] = lo;
            }
        }
    }
}

// ---------------------------------------------------------------------------
// Fused H prepass: one read of H produces both packings.
// ---------------------------------------------------------------------------
__global__ void prep_H(const float* __restrict__ H) {
    __shared__ float t[32][33];
    const int b = blockIdx.z;
    const float* src = H + (size_t)b * T_ * HD;
    const int r0 = blockIdx.x * 32;   // T dim
    const int c0 = blockIdx.y * 32;   // HD dim
    const int tx = threadIdx.x, ty = threadIdx.y;

    #pragma unroll
    for (int i = 0; i < 4; i++) {
        int r = r0 + ty + i * 8;
        t[ty + i * 8][tx] = (r < T_) ? src[(size_t)r * HD + c0 + tx] : 0.f;
    }
    __syncthreads();
    if (tx < 16) {
        #pragma unroll
        for (int i = 0; i < 4; i++) {
            int cc = ty + i * 8, c = c0 + cc;
            uint32_t hi, lo;
            split_pair(t[2 * tx][cc], t[2 * tx + 1][cc], hi, lo);
            size_t o = ((size_t)b * HD + c) * TP2 + (r0 >> 1) + tx;
            g_Hth[o] = hi;
            g_Htl[o] = lo;
        }
        #pragma unroll
        for (int i = 0; i < 4; i++) {
            int rr = ty + i * 8, r = r0 + rr;
            if (r < T_) {
                uint32_t hi, lo;
                split_pair(t[rr][2 * tx], t[rr][2 * tx + 1], hi, lo);
                size_t o = ((size_t)b * T_ + r) * HP2 + (c0 >> 1) + tx;
                g_Hh[o] = hi;
                g_Hl[o] = lo;
            }
        }
    }
}

// ---------------------------------------------------------------------------
// bf16 split-compensated tensor-core GEMM (NT, packed hi/lo operands).
//   C[b] = alpha * A[b] (M x Kp) @ B[b] (N x Kp)^T,  products hh+hl+lh
// BM=128, BN=64, BK=32, 256 threads (8 warps, 4x2), warp tile 32x32.
// 4-stage cp.async pipeline; pitch-16 XOR-swizzled smem (no padding).
//   row r, k-group c4 (4 u32 each): stored at group c4 ^ ((r>>1)&3)
// Stage layout (u32): Ah[0,2048) Al[2048,4096) Bh[4096,5120) Bl[5120,6144)
// ---------------------------------------------------------------------------
template<bool OSPLIT>
__global__ __launch_bounds__(256, 2)
void gemm_bf16s(const uint32_t* __restrict__ Ah, const uint32_t* __restrict__ Al, size_t sA,
                const uint32_t* __restrict__ Bh, const uint32_t* __restrict__ Bl, size_t sB,
                float* __restrict__ Cf, uint32_t* __restrict__ Ch, uint32_t* __restrict__ Cl,
                size_t sC, int M, int N, int Kp, float alpha)
{
    constexpr int STG_U32  = 6144;            // 24 KB per stage
    constexpr int STG_B    = STG_U32 * 4;
    constexpr int NSTAGE   = 4;

    extern __shared__ uint32_t sm[];
    const uint32_t sbase = (uint32_t)__cvta_generic_to_shared(sm);

    const int b = blockIdx.z;
    Ah += sA * b;  Al += sA * b;
    Bh += sB * b;  Bl += sB * b;
    const int m0 = blockIdx.x * 128;
    const int n0 = blockIdx.y * 64;
    const int tid  = threadIdx.x;
    const int warp = tid >> 5, lane = tid & 31;
    const int wm = warp >> 1, wn = warp & 1;       // 4 x 2 warp grid
    const int l4 = lane >> 2, lk = lane & 3;
    const int Kp2 = Kp >> 1;

    // ---- per-lane ldmatrix addresses (stage 0, kk=0, hi arrays), bytes ----
    const int lt = lane >> 3, lr = lane & 7;
    const int rowA = (lt & 1) * 8 + lr;   // 0..15 within 16-row tile
    const int gA   = lt >> 1;             // k-subgroup 0/1
    const int rowB = (lt >> 1) * 8 + lr;
    const int gB   = lt & 1;

    uint32_t aAddr[2], bAddr[2];
    #pragma unroll
    for (int mi = 0; mi < 2; mi++) {
        int r = wm * 32 + mi * 16 + rowA;
        int sw = (r >> 1) & 3;
        aAddr[mi] = (uint32_t)((r * 16 + ((gA ^ sw) * 4)) << 2);
    }
    #pragma unroll
    for (int pr = 0; pr < 2; pr++) {
        int r = wn * 32 + pr * 16 + rowB;
        int sw = (r >> 1) & 3;
        bAddr[pr] = (uint32_t)(((4096 + r * 16 + ((gB ^ sw) * 4))) << 2);
    }

    float acc[2][4][4] = {};
    const int nck = Kp >> 5;

    auto load_tile = [&](int ck, int st) {
        const uint32_t stg = sbase + (uint32_t)(st * STG_B);
        const int k0 = ck * 16;
        // A: 1024 chunks (2 arrays x 128 rows x 4 groups)
        #pragma unroll
        for (int i = 0; i < 4; i++) {
            int idx = tid + i * 256;
            int arr = idx >> 9, rem = idx & 511;
            int r = rem >> 2, c4 = rem & 3;
            int sw = c4 ^ ((r >> 1) & 3);
            int gm = m0 + r;
            bool ok = gm < M;
            const uint32_t* base = arr ? Al : Ah;
            const uint32_t* src = ok ? (base + (size_t)gm * Kp2 + k0 + c4 * 4) : base;
            cp16(stg + ((arr * 2048 + r * 16 + sw * 4) << 2), src, ok);
        }
        // B: 512 chunks (2 arrays x 64 rows x 4 groups)
        #pragma unroll
        for (int i = 0; i < 2; i++) {
            int idx = tid + i * 256;
            int arr = idx >> 8, rem = idx & 255;
            int r = rem >> 2, c4 = rem & 3;
            int sw = c4 ^ ((r >> 1) & 3);
            int gn = n0 + r;
            bool ok = gn < N;
            const uint32_t* base = arr ? Bl : Bh;
            const uint32_t* src = ok ? (base + (size_t)gn * Kp2 + k0 + c4 * 4) : base;
            cp16(stg + ((4096 + arr * 1024 + r * 16 + sw * 4) << 2), src, ok);
        }
    };

    // prologue: fill 3 stages (empty groups where ck >= nck)
    #pragma unroll
    for (int p = 0; p < NSTAGE - 1; p++) {
        if (p < nck) load_tile(p, p);
        CP_COMMIT();
    }

    for (int ck = 0; ck < nck; ck++) {
        asm volatile("cp.async.wait_group %0;" :: "n"(NSTAGE - 2) : "memory");
        __syncthreads();

        // issue load for ck+3 into stage (ck+3)%4 (buffer of ck-1, all done)
        if (ck + NSTAGE - 1 < nck) load_tile(ck + NSTAGE - 1, (ck + NSTAGE - 1) & 3);
        CP_COMMIT();

        const uint32_t stg = sbase + (uint32_t)((ck & 3) * STG_B);

        #pragma unroll
        for (int kk = 0; kk < 2; kk++) {
            const uint32_t kx = kk ? 32u : 0u;   // k-subgroup pair toggle (XOR-safe)
            uint32_t a_h[2][4], a_l[2][4], b_h[4][2], b_l[4][2];
            #pragma unroll
            for (int mi = 0; mi < 2; mi++) {
                uint32_t ad = (stg + aAddr[mi]) ^ kx;
                ldsm4(a_h[mi], ad);
                ldsm4(a_l[mi], ad + 8192);
            }
            #pragma unroll
            for (int pr = 0; pr < 2; pr++) {
                uint32_t bd = (stg + bAddr[pr]) ^ kx;
                uint32_t bt[4];
                ldsm4(bt, bd);
                b_h[2 * pr][0] = bt[0]; b_h[2 * pr][1] = bt[1];
                b_h[2 * pr + 1][0] = bt[2]; b_h[2 * pr + 1][1] = bt[3];
                ldsm4(bt, bd + 4096);
                b_l[2 * pr][0] = bt[0]; b_l[2 * pr][1] = bt[1];
                b_l[2 * pr + 1][0] = bt[2]; b_l[2 * pr + 1][1] = bt[3];
            }
            #pragma unroll
            for (int mi = 0; mi < 2; mi++)
                #pragma unroll
                for (int ni = 0; ni < 4; ni++) {
                    mma_bf16(acc[mi][ni], a_h[mi], b_h[ni]);
                    mma_bf16(acc[mi][ni], a_h[mi], b_l[ni]);
                    mma_bf16(acc[mi][ni], a_l[mi], b_h[ni]);
                }
        }
    }

    // ---- epilogue ----
    const int N2 = N >> 1;
    #pragma unroll
    for (int mi = 0; mi < 2; mi++) {
        #pragma unroll
        for (int ni = 0; ni < 4; ni++) {
            int r0 = m0 + wm * 32 + mi * 16 + l4;
            int c0 = n0 + wn * 32 + ni * 8 + 2 * lk;
            if (c0 < N) {
                if (OSPLIT) {
                    int pj = c0 >> 1;
                    if (r0 < M) {
                        uint32_t hi, lo;
                        split_pair(alpha * acc[mi][ni][0], alpha * acc[mi][ni][1], hi, lo);
                        Ch[sC * b + (size_t)r0 * N2 + pj] = hi;
                        Cl[sC * b + (size_t)r0 * N2 + pj] = lo;
                    }
                    if (r0 + 8 < M) {
                        uint32_t hi, lo;
                        split_pair(alpha * acc[mi][ni][2], alpha * acc[mi][ni][3], hi, lo);
                        Ch[sC * b + (size_t)(r0 + 8) * N2 + pj] = hi;
                        Cl[sC * b + (size_t)(r0 + 8) * N2 + pj] = lo;
                    }
                } else {
                    if (r0 < M) {
                        float2 v = make_float2(alpha * acc[mi][ni][0], alpha * acc[mi][ni][1]);
                        *reinterpret_cast<float2*>(Cf + sC * b + (size_t)r0 * N + c0) = v;
                    }
                    if (r0 + 8 < M) {
                        float2 v = make_float2(alpha * acc[mi][ni][2], alpha * acc[mi][ni][3]);
                        *reinterpret_cast<float2*>(Cf + sC * b + (size_t)(r0 + 8) * N + c0) = v;
                    }
                }
            }
        }
    }
}

// ---------------------------------------------------------------------------
// Softmax rows of g_L -> split-packed probs g_Ph/g_Pl (zero-padded).
// ---------------------------------------------------------------------------
__global__ void softmax_split() {
    const size_t row = (size_t)blockIdx.y * CN + blockIdx.x;
    const float* Lr = g_L + row * T_;
    const float4* p4 = reinterpret_cast<const float4*>(Lr);
    constexpr int N4 = T_ / 4;   // 345
    const int tid = threadIdx.x;
    const int lane = tid & 31, warp = tid >> 5;
    __shared__ float red[8];

    float m = -CUDART_INF_F;
    for (int i = tid; i < N4; i += 256) {
        float4 v = p4[i];
        m = fmaxf(m, fmaxf(fmaxf(v.x, v.y), fmaxf(v.z, v.w)));
    }
    #pragma unroll
    for (int o = 16; o > 0; o >>= 1) m = fmaxf(m, __shfl_xor_sync(0xffffffffu, m, o));
    if (lane == 0) red[warp] = m;
    __syncthreads();
    float M = red[0];
    #pragma unroll
    for (int j = 1; j < 8; j++) M = fmaxf(M, red[j]);
    __syncthreads();

    float s = 0.f;
    for (int i = tid; i < N4; i += 256) {
        float4 v = p4[i];
        s += __expf(v.x - M) + __expf(v.y - M) + __expf(v.z - M) + __expf(v.w - M);
    }
    #pragma unroll
    for (int o = 16; o > 0; o >>= 1) s += __shfl_xor_sync(0xffffffffu, s, o);
    if (lane == 0) red[warp] = s;
    __syncthreads();
    float S = red[0];
    #pragma unroll
    for (int j = 1; j < 8; j++) S += red[j];
    float inv = __frcp_rn(S);

    uint32_t* Ph = g_Ph + row * TP2;
    uint32_t* Pl = g_Pl + row * TP2;
    const float2* p2 = reinterpret_cast<const float2*>(Lr);
    for (int j = tid; j < TP2; j += 256) {
        uint32_t hi = 0, lo = 0;
        if (j < T2) {
            float2 v = p2[j];
            split_pair(__expf(v.x - M) * inv, __expf(v.y - M) * inv, hi, lo);
        }
        Ph[j] = hi;
        Pl[j] = lo;
    }
}

// ---------------------------------------------------------------------------

static inline int cdiv(int a, int b) { return (a + b - 1) / b; }

extern "C" void kernel_launch(void* const* d_in, const int* in_sizes, int n_in,
                              void* d_out, int out_size) {
    const float* X  = (const float*)d_in[0];  // [B,T,XD]
    const float* H  = (const float*)d_in[1];  // [B,T,HD]
    const float* W1 = (const float*)d_in[2];  // [XD,HD]
    const float* W2 = (const float*)d_in[3];  // [CN,T]
    float* out = (float*)d_out;               // [B,CN,HD]

    uint32_t *W2h, *W2l, *Xth, *Xtl, *W1th, *W1tl, *Hh, *Hl, *Hth, *Htl;
    uint32_t *Zh, *Zl, *Yh, *Yl, *Ph, *Pl;
    float* L;
    cudaGetSymbolAddress((void**)&W2h, g_W2h);  cudaGetSymbolAddress((void**)&W2l, g_W2l);
    cudaGetSymbolAddress((void**)&Xth, g_Xth);  cudaGetSymbolAddress((void**)&Xtl, g_Xtl);
    cudaGetSymbolAddress((void**)&W1th, g_W1th); cudaGetSymbolAddress((void**)&W1tl, g_W1tl);
    cudaGetSymbolAddress((void**)&Hh, g_Hh);    cudaGetSymbolAddress((void**)&Hl, g_Hl);
    cudaGetSymbolAddress((void**)&Hth, g_Hth);  cudaGetSymbolAddress((void**)&Htl, g_Htl);
    cudaGetSymbolAddress((void**)&Zh, g_Zh);    cudaGetSymbolAddress((void**)&Zl, g_Zl);
    cudaGetSymbolAddress((void**)&Yh, g_Yh);    cudaGetSymbolAddress((void**)&Yl, g_Yl);
    cudaGetSymbolAddress((void**)&Ph, g_Ph);    cudaGetSymbolAddress((void**)&Pl, g_Pl);
    cudaGetSymbolAddress((void**)&L,  g_L);

    const float scale = 1.0f / sqrtf((float)XD * (float)HD);

    constexpr int SMEM = 4 * 6144 * 4;   // 98304 B (4 stages x 24 KB)

    static bool attr_done = false;
    if (!attr_done) {
        cudaFuncSetAttribute(gemm_bf16s<true>,
            cudaFuncAttributeMaxDynamicSharedMemorySize, SMEM);
        cudaFuncSetAttribute(gemm_bf16s<false>,
            cudaFuncAttributeMaxDynamicSharedMemorySize, SMEM);
        attr_done = true;
    }

    // ---- prepass ----
    {
        size_t tot = (size_t)CN * TP2;
        split_pack<<<(int)cdiv((int)tot, 256), 256>>>(W2, W2h, W2l, CN, T_, TP2);
    }
    prep_H<<<dim3(TP / 32, HD / 32, B_), dim3(32, 8)>>>(H);
    split_transpose<<<dim3(TP / 32, cdiv(XD, 32), B_), dim3(32, 8)>>>(
        X, (size_t)T_ * XD, Xth, Xtl, (size_t)XD * TP2, T_, XD, TP2);
    split_transpose<<<dim3(XD / 32, cdiv(HD, 32), 1), dim3(32, 8)>>>(
        W1, 0, W1th, W1tl, 0, XD, HD, XP2);

    // 1) Z[b] = W2 @ X[b]       A=W2 [CN,TP], B=Xt [XD,TP] -> Z split [CN,XP2]
    gemm_bf16s<true><<<dim3(cdiv(CN, 128), cdiv(XD, 64), B_), 256, SMEM>>>(
        W2h, W2l, 0, Xth, Xtl, (size_t)XD * TP2,
        nullptr, Zh, Zl, (size_t)CN * XP2, CN, XD, TP, 1.0f);

    // 2) Y[b] = Z[b] @ W1       A=Z [CN,XD], B=W1t [HD,XD] -> Y split [CN,HP2]
    gemm_bf16s<true><<<dim3(cdiv(CN, 128), cdiv(HD, 64), B_), 256, SMEM>>>(
        Zh, Zl, (size_t)CN * XP2, W1th, W1tl, 0,
        nullptr, Yh, Yl, (size_t)CN * HP2, CN, HD, XD, 1.0f);

    // 3) L[b] = scale * Y[b] @ H[b]^T   A=Y [CN,HD], B=H [T,HD] -> L fp32
    gemm_bf16s<false><<<dim3(cdiv(CN, 128), cdiv(T_, 64), B_), 256, SMEM>>>(
        Yh, Yl, (size_t)CN * HP2, Hh, Hl, (size_t)T_ * HP2,
        L, nullptr, nullptr, (size_t)CN * T_, CN, T_, HD, scale);

    // 4) softmax rows of L -> P split [CN,TP2]
    softmax_split<<<dim3(CN, B_), 256>>>();

    // 5) out[b] = P[b] @ H[b]   A=P [CN,TP], B=Ht [HD,TP] -> out fp32
    gemm_bf16s<false><<<dim3(cdiv(CN, 128), cdiv(HD, 64), B_), 256, SMEM>>>(
        Ph, Pl, (size_t)CN * TP2, Hth, Htl, (size_t)HD * TP2,
        out, nullptr, nullptr, (size_t)CN * HD, CN, HD, TP, 1.0f);
}

// round 11
// speedup vs baseline: 1.6029x; 1.1210x over previous
#include <cuda_runtime.h>
#include <cuda_bf16.h>
#include <math_constants.h>
#include <cstdint>

#define B_  64
#define T_  1380
#define TP  1408        // T padded to multiple of 32
#define TP2 (TP/2)      // 704 packed pairs
#define XD  96
#define XP2 (XD/2)      // 48
#define HD  192
#define HP2 (HD/2)      // 96
#define CN  345

#define P_THRESH 1e-8f

// ---------------------------------------------------------------------------
// Scratch (device globals). hi/lo bf16 pairs packed in uint32 (low = lower k).
// ---------------------------------------------------------------------------
__device__ uint32_t g_W2h[(size_t)CN * TP2],      g_W2l[(size_t)CN * TP2];
__device__ uint32_t g_Xth[(size_t)B_ * XD * TP2], g_Xtl[(size_t)B_ * XD * TP2];
__device__ uint32_t g_W1th[(size_t)HD * XP2],     g_W1tl[(size_t)HD * XP2];
__device__ uint32_t g_Hh [(size_t)B_ * T_ * HP2], g_Hl [(size_t)B_ * T_ * HP2];
__device__ uint32_t g_Zh [(size_t)B_ * CN * XP2], g_Zl [(size_t)B_ * CN * XP2];
__device__ uint32_t g_Yh [(size_t)B_ * CN * HP2], g_Yl [(size_t)B_ * CN * HP2];
__device__ float    g_L  [(size_t)B_ * CN * T_];

// ---------------------------------------------------------------------------
// Helpers
// ---------------------------------------------------------------------------
__device__ __forceinline__ void split_pair(float x0, float x1,
                                           uint32_t& hi, uint32_t& lo) {
    __nv_bfloat16 h0 = __float2bfloat16_rn(x0);
    __nv_bfloat16 h1 = __float2bfloat16_rn(x1);
    float r0 = x0 - __bfloat162float(h0);
    float r1 = x1 - __bfloat162float(h1);
    __nv_bfloat16 l0 = __float2bfloat16_rn(r0);
    __nv_bfloat16 l1 = __float2bfloat16_rn(r1);
    hi = ((uint32_t)__bfloat16_as_ushort(h1) << 16) | __bfloat16_as_ushort(h0);
    lo = ((uint32_t)__bfloat16_as_ushort(l1) << 16) | __bfloat16_as_ushort(l0);
}

__device__ __forceinline__ void mma_bf16(float* c, const uint32_t* a, const uint32_t* b) {
    asm volatile(
        "mma.sync.aligned.m16n8k16.row.col.f32.bf16.bf16.f32 "
        "{%0,%1,%2,%3}, {%4,%5,%6,%7}, {%8,%9}, {%0,%1,%2,%3};"
        : "+f"(c[0]), "+f"(c[1]), "+f"(c[2]), "+f"(c[3])
        : "r"(a[0]), "r"(a[1]), "r"(a[2]), "r"(a[3]),
          "r"(b[0]), "r"(b[1]));
}

__device__ __forceinline__ void ldsm4(uint32_t* r, uint32_t saddr) {
    asm volatile("ldmatrix.sync.aligned.m8n8.x4.shared.b16 {%0,%1,%2,%3}, [%4];"
                 : "=r"(r[0]), "=r"(r[1]), "=r"(r[2]), "=r"(r[3]) : "r"(saddr));
}

__device__ __forceinline__ void cp16(uint32_t dst, const void* src, bool ok) {
    asm volatile(
        "{\n\t.reg .pred p;\n\t.reg .b32 sz;\n\t"
        "setp.ne.u32 p, %2, 0;\n\t"
        "selp.b32 sz, 16, 0, p;\n\t"
        "cp.async.cg.shared.global [%0], [%1], 16, sz;\n\t}"
        :: "r"(dst), "l"(src), "r"((uint32_t)ok) : "memory");
}
#define CP_COMMIT() asm volatile("cp.async.commit_group;" ::: "memory")

// ---------------------------------------------------------------------------
// Prepass: elementwise split+pack (zero-pad cols to Cp2 pairs)
// ---------------------------------------------------------------------------
__global__ void split_pack(const float* __restrict__ src,
                           uint32_t* __restrict__ dh, uint32_t* __restrict__ dl,
                           int rows, int C, int Cp2) {
    size_t idx = (size_t)blockIdx.x * 256 + threadIdx.x;
    size_t total = (size_t)rows * Cp2;
    if (idx >= total) return;
    int r = (int)(idx / Cp2);
    int j = (int)(idx - (size_t)r * Cp2);
    float2 v = make_float2(0.f, 0.f);
    if (2 * j < C)
        v = *reinterpret_cast<const float2*>(src + (size_t)r * C + 2 * j);
    uint32_t hi, lo;
    split_pair(v.x, v.y, hi, lo);
    dh[idx] = hi;
    dl[idx] = lo;
}

// ---------------------------------------------------------------------------
// Prepass: split + transpose + pack.  src [b][R][C] -> [b][C][Rp2]
// ---------------------------------------------------------------------------
__global__ void split_transpose(const float* __restrict__ src, size_t sSrc,
                                uint32_t* __restrict__ dh, uint32_t* __restrict__ dl,
                                size_t sDst, int R, int C, int Rp2) {
    __shared__ float t[32][33];
    const int b = blockIdx.z;
    src += sSrc * b;
    dh  += sDst * b;
    dl  += sDst * b;
    const int r0 = blockIdx.x * 32;
    const int c0 = blockIdx.y * 32;
    const int tx = threadIdx.x, ty = threadIdx.y;

    #pragma unroll
    for (int i = 0; i < 4; i++) {
        int r = r0 + ty + i * 8, c = c0 + tx;
        t[ty + i * 8][tx] = (r < R && c < C) ? src[(size_t)r * C + c] : 0.f;
    }
    __syncthreads();
    if (tx < 16) {
        #pragma unroll
        for (int i = 0; i < 4; i++) {
            int cc = ty + i * 8, c = c0 + cc;
            if (c < C) {
                uint32_t hi, lo;
                split_pair(t[2 * tx][cc], t[2 * tx + 1][cc], hi, lo);
                size_t o = (size_t)c * Rp2 + (r0 >> 1) + tx;
                dh[o] = hi;
                dl[o] = lo;
            }
        }
    }
}

// ---------------------------------------------------------------------------
// bf16 split-compensated tensor-core GEMM (NT, packed hi/lo operands).
//   C[b] = alpha * A[b] (M x Kp) @ B[b] (N x Kp)^T,  products hh+hl+lh
// BM=128, BN=64, BK=32, 256 threads (8 warps, 4x2), warp tile 32x32.
// 4-stage cp.async pipeline; pitch-16 XOR-swizzled smem (no padding).
// Stage layout (u32): Ah[0,2048) Al[2048,4096) Bh[4096,5120) Bl[5120,6144)
// ---------------------------------------------------------------------------
template<bool OSPLIT>
__global__ __launch_bounds__(256, 2)
void gemm_bf16s(const uint32_t* __restrict__ Ah, const uint32_t* __restrict__ Al, size_t sA,
                const uint32_t* __restrict__ Bh, const uint32_t* __restrict__ Bl, size_t sB,
                float* __restrict__ Cf, uint32_t* __restrict__ Ch, uint32_t* __restrict__ Cl,
                size_t sC, int M, int N, int Kp, float alpha)
{
    constexpr int STG_U32  = 6144;            // 24 KB per stage
    constexpr int STG_B    = STG_U32 * 4;
    constexpr int NSTAGE   = 4;

    extern __shared__ uint32_t sm[];
    const uint32_t sbase = (uint32_t)__cvta_generic_to_shared(sm);

    const int b = blockIdx.z;
    Ah += sA * b;  Al += sA * b;
    Bh += sB * b;  Bl += sB * b;
    const int m0 = blockIdx.x * 128;
    const int n0 = blockIdx.y * 64;
    const int tid  = threadIdx.x;
    const int warp = tid >> 5, lane = tid & 31;
    const int wm = warp >> 1, wn = warp & 1;       // 4 x 2 warp grid
    const int l4 = lane >> 2, lk = lane & 3;
    const int Kp2 = Kp >> 1;

    // ---- per-lane ldmatrix addresses (stage 0, kk=0, hi arrays), bytes ----
    const int lt = lane >> 3, lr = lane & 7;
    const int rowA = (lt & 1) * 8 + lr;
    const int gA   = lt >> 1;
    const int rowB = (lt >> 1) * 8 + lr;
    const int gB   = lt & 1;

    uint32_t aAddr[2], bAddr[2];
    #pragma unroll
    for (int mi = 0; mi < 2; mi++) {
        int r = wm * 32 + mi * 16 + rowA;
        int sw = (r >> 1) & 3;
        aAddr[mi] = (uint32_t)((r * 16 + ((gA ^ sw) * 4)) << 2);
    }
    #pragma unroll
    for (int pr = 0; pr < 2; pr++) {
        int r = wn * 32 + pr * 16 + rowB;
        int sw = (r >> 1) & 3;
        bAddr[pr] = (uint32_t)(((4096 + r * 16 + ((gB ^ sw) * 4))) << 2);
    }

    float acc[2][4][4] = {};
    const int nck = Kp >> 5;

    auto load_tile = [&](int ck, int st) {
        const uint32_t stg = sbase + (uint32_t)(st * STG_B);
        const int k0 = ck * 16;
        #pragma unroll
        for (int i = 0; i < 4; i++) {
            int idx = tid + i * 256;
            int arr = idx >> 9, rem = idx & 511;
            int r = rem >> 2, c4 = rem & 3;
            int sw = c4 ^ ((r >> 1) & 3);
            int gm = m0 + r;
            bool ok = gm < M;
            const uint32_t* base = arr ? Al : Ah;
            const uint32_t* src = ok ? (base + (size_t)gm * Kp2 + k0 + c4 * 4) : base;
            cp16(stg + ((arr * 2048 + r * 16 + sw * 4) << 2), src, ok);
        }
        #pragma unroll
        for (int i = 0; i < 2; i++) {
            int idx = tid + i * 256;
            int arr = idx >> 8, rem = idx & 255;
            int r = rem >> 2, c4 = rem & 3;
            int sw = c4 ^ ((r >> 1) & 3);
            int gn = n0 + r;
            bool ok = gn < N;
            const uint32_t* base = arr ? Bl : Bh;
            const uint32_t* src = ok ? (base + (size_t)gn * Kp2 + k0 + c4 * 4) : base;
            cp16(stg + ((4096 + arr * 1024 + r * 16 + sw * 4) << 2), src, ok);
        }
    };

    #pragma unroll
    for (int p = 0; p < NSTAGE - 1; p++) {
        if (p < nck) load_tile(p, p);
        CP_COMMIT();
    }

    for (int ck = 0; ck < nck; ck++) {
        asm volatile("cp.async.wait_group %0;" :: "n"(NSTAGE - 2) : "memory");
        __syncthreads();

        if (ck + NSTAGE - 1 < nck) load_tile(ck + NSTAGE - 1, (ck + NSTAGE - 1) & 3);
        CP_COMMIT();

        const uint32_t stg = sbase + (uint32_t)((ck & 3) * STG_B);

        #pragma unroll
        for (int kk = 0; kk < 2; kk++) {
            const uint32_t kx = kk ? 32u : 0u;
            uint32_t a_h[2][4], a_l[2][4], b_h[4][2], b_l[4][2];
            #pragma unroll
            for (int mi = 0; mi < 2; mi++) {
                uint32_t ad = (stg + aAddr[mi]) ^ kx;
                ldsm4(a_h[mi], ad);
                ldsm4(a_l[mi], ad + 8192);
            }
            #pragma unroll
            for (int pr = 0; pr < 2; pr++) {
                uint32_t bd = (stg + bAddr[pr]) ^ kx;
                uint32_t bt[4];
                ldsm4(bt, bd);
                b_h[2 * pr][0] = bt[0]; b_h[2 * pr][1] = bt[1];
                b_h[2 * pr + 1][0] = bt[2]; b_h[2 * pr + 1][1] = bt[3];
                ldsm4(bt, bd + 4096);
                b_l[2 * pr][0] = bt[0]; b_l[2 * pr][1] = bt[1];
                b_l[2 * pr + 1][0] = bt[2]; b_l[2 * pr + 1][1] = bt[3];
            }
            #pragma unroll
            for (int mi = 0; mi < 2; mi++)
                #pragma unroll
                for (int ni = 0; ni < 4; ni++) {
                    mma_bf16(acc[mi][ni], a_h[mi], b_h[ni]);
                    mma_bf16(acc[mi][ni], a_h[mi], b_l[ni]);
                    mma_bf16(acc[mi][ni], a_l[mi], b_h[ni]);
                }
        }
    }

    // ---- epilogue ----
    const int N2 = N >> 1;
    #pragma unroll
    for (int mi = 0; mi < 2; mi++) {
        #pragma unroll
        for (int ni = 0; ni < 4; ni++) {
            int r0 = m0 + wm * 32 + mi * 16 + l4;
            int c0 = n0 + wn * 32 + ni * 8 + 2 * lk;
            if (c0 < N) {
                if (OSPLIT) {
                    int pj = c0 >> 1;
                    if (r0 < M) {
                        uint32_t hi, lo;
                        split_pair(alpha * acc[mi][ni][0], alpha * acc[mi][ni][1], hi, lo);
                        Ch[sC * b + (size_t)r0 * N2 + pj] = hi;
                        Cl[sC * b + (size_t)r0 * N2 + pj] = lo;
                    }
                    if (r0 + 8 < M) {
                        uint32_t hi, lo;
                        split_pair(alpha * acc[mi][ni][2], alpha * acc[mi][ni][3], hi, lo);
                        Ch[sC * b + (size_t)(r0 + 8) * N2 + pj] = hi;
                        Cl[sC * b + (size_t)(r0 + 8) * N2 + pj] = lo;
                    }
                } else {
                    if (r0 < M) {
                        float2 v = make_float2(alpha * acc[mi][ni][0], alpha * acc[mi][ni][1]);
                        *reinterpret_cast<float2*>(Cf + sC * b + (size_t)r0 * N + c0) = v;
                    }
                    if (r0 + 8 < M) {
                        float2 v = make_float2(alpha * acc[mi][ni][2], alpha * acc[mi][ni][3]);
                        *reinterpret_cast<float2*>(Cf + sC * b + (size_t)(r0 + 8) * N + c0) = v;
                    }
                }
            }
        }
    }
}

// ---------------------------------------------------------------------------
// Softmax + sparse gather. One block per (c, b) row of L.
// Softmax mass is concentrated (logits ~ N(0,37^2)): keep p > P_THRESH
// (dropped mass provably <= T * P_THRESH = 1.38e-5), then
//   out[b,c,:] = sum_i p_i * H[b, u_i, :]
// Compaction is warp-ballot ordered (deterministic); smem list sized to T.
// ---------------------------------------------------------------------------
__global__ void softmax_gather(const float* __restrict__ H,
                               float* __restrict__ out) {
    const int c = blockIdx.x, b = blockIdx.y;
    const size_t row = (size_t)b * CN + c;
    const float* Lr = g_L + row * T_;
    const float4* p4 = reinterpret_cast<const float4*>(Lr);
    constexpr int N4 = T_ / 4;   // 345
    const int tid = threadIdx.x;
    const int lane = tid & 31, warp = tid >> 5;

    __shared__ float red[8];
    __shared__ int cnt;
    __shared__ uint32_t sidx[T_];
    __shared__ float    sval[T_];

    // 1) max
    float m = -CUDART_INF_F;
    for (int i = tid; i < N4; i += 256) {
        float4 v = p4[i];
        m = fmaxf(m, fmaxf(fmaxf(v.x, v.y), fmaxf(v.z, v.w)));
    }
    #pragma unroll
    for (int o = 16; o > 0; o >>= 1) m = fmaxf(m, __shfl_xor_sync(0xffffffffu, m, o));
    if (lane == 0) red[warp] = m;
    __syncthreads();
    float M = red[0];
    #pragma unroll
    for (int j = 1; j < 8; j++) M = fmaxf(M, red[j]);
    __syncthreads();

    // 2) sum of exp
    float s = 0.f;
    for (int i = tid; i < N4; i += 256) {
        float4 v = p4[i];
        s += __expf(v.x - M) + __expf(v.y - M) + __expf(v.z - M) + __expf(v.w - M);
    }
    #pragma unroll
    for (int o = 16; o > 0; o >>= 1) s += __shfl_xor_sync(0xffffffffu, s, o);
    if (lane == 0) red[warp] = s;
    __syncthreads();
    float S = red[0];
    #pragma unroll
    for (int j = 1; j < 8; j++) S += red[j];
    const float inv = __frcp_rn(S);

    // 3) ordered compaction of p > P_THRESH (warp 0 only; deterministic)
    if (warp == 0) {
        int base = 0;
        for (int i0 = 0; i0 < T_; i0 += 32) {
            int i = i0 + lane;
            float p = (i < T_) ? __expf(Lr[i] - M) * inv : 0.f;
            unsigned bal = __ballot_sync(0xffffffffu, p > P_THRESH);
            int off = __popc(bal & ((1u << lane) - 1u));
            if (p > P_THRESH) { sidx[base + off] = (uint32_t)i; sval[base + off] = p; }
            base += __popc(bal);
        }
        if (lane == 0) cnt = base;
    }
    __syncthreads();

    // 4) gather: out row = sum of kept p_i * H rows (fixed order -> deterministic)
    const int n = cnt;
    const float* Hb = H + (size_t)b * T_ * HD;
    float* Orow = out + row * HD;
    for (int j = tid; j < HD; j += 256) {
        float acc = 0.f;
        for (int k = 0; k < n; k++)
            acc += sval[k] * Hb[(size_t)sidx[k] * HD + j];
        Orow[j] = acc;
    }
}

// ---------------------------------------------------------------------------

static inline int cdiv(int a, int b) { return (a + b - 1) / b; }

extern "C" void kernel_launch(void* const* d_in, const int* in_sizes, int n_in,
                              void* d_out, int out_size) {
    const float* X  = (const float*)d_in[0];  // [B,T,XD]
    const float* H  = (const float*)d_in[1];  // [B,T,HD]
    const float* W1 = (const float*)d_in[2];  // [XD,HD]
    const float* W2 = (const float*)d_in[3];  // [CN,T]
    float* out = (float*)d_out;               // [B,CN,HD]

    uint32_t *W2h, *W2l, *Xth, *Xtl, *W1th, *W1tl, *Hh, *Hl;
    uint32_t *Zh, *Zl, *Yh, *Yl;
    float* L;
    cudaGetSymbolAddress((void**)&W2h, g_W2h);  cudaGetSymbolAddress((void**)&W2l, g_W2l);
    cudaGetSymbolAddress((void**)&Xth, g_Xth);  cudaGetSymbolAddress((void**)&Xtl, g_Xtl);
    cudaGetSymbolAddress((void**)&W1th, g_W1th); cudaGetSymbolAddress((void**)&W1tl, g_W1tl);
    cudaGetSymbolAddress((void**)&Hh, g_Hh);    cudaGetSymbolAddress((void**)&Hl, g_Hl);
    cudaGetSymbolAddress((void**)&Zh, g_Zh);    cudaGetSymbolAddress((void**)&Zl, g_Zl);
    cudaGetSymbolAddress((void**)&Yh, g_Yh);    cudaGetSymbolAddress((void**)&Yl, g_Yl);
    cudaGetSymbolAddress((void**)&L,  g_L);

    const float scale = 1.0f / sqrtf((float)XD * (float)HD);

    constexpr int SMEM = 4 * 6144 * 4;   // 98304 B (4 stages x 24 KB)

    static bool attr_done = false;
    if (!attr_done) {
        cudaFuncSetAttribute(gemm_bf16s<true>,
            cudaFuncAttributeMaxDynamicSharedMemorySize, SMEM);
        cudaFuncSetAttribute(gemm_bf16s<false>,
            cudaFuncAttributeMaxDynamicSharedMemorySize, SMEM);
        attr_done = true;
    }

    // ---- prepass ----
    {
        size_t tot = (size_t)CN * TP2;
        split_pack<<<(int)cdiv((int)tot, 256), 256>>>(W2, W2h, W2l, CN, T_, TP2);
    }
    {
        size_t tot = (size_t)B_ * T_ * HP2;    // H direct pack only
        split_pack<<<(int)((tot + 255) / 256), 256>>>(H, Hh, Hl, B_ * T_, HD, HP2);
    }
    split_transpose<<<dim3(TP / 32, cdiv(XD, 32), B_), dim3(32, 8)>>>(
        X, (size_t)T_ * XD, Xth, Xtl, (size_t)XD * TP2, T_, XD, TP2);
    split_transpose<<<dim3(XD / 32, cdiv(HD, 32), 1), dim3(32, 8)>>>(
        W1, 0, W1th, W1tl, 0, XD, HD, XP2);

    // 1) Z[b] = W2 @ X[b]       A=W2 [CN,TP], B=Xt [XD,TP] -> Z split [CN,XP2]
    gemm_bf16s<true><<<dim3(cdiv(CN, 128), cdiv(XD, 64), B_), 256, SMEM>>>(
        W2h, W2l, 0, Xth, Xtl, (size_t)XD * TP2,
        nullptr, Zh, Zl, (size_t)CN * XP2, CN, XD, TP, 1.0f);

    // 2) Y[b] = Z[b] @ W1       A=Z [CN,XD], B=W1t [HD,XD] -> Y split [CN,HP2]
    gemm_bf16s<true><<<dim3(cdiv(CN, 128), cdiv(HD, 64), B_), 256, SMEM>>>(
        Zh, Zl, (size_t)CN * XP2, W1th, W1tl, 0,
        nullptr, Yh, Yl, (size_t)CN * HP2, CN, HD, XD, 1.0f);

    // 3) L[b] = scale * Y[b] @ H[b]^T   A=Y [CN,HD], B=H [T,HD] -> L fp32
    gemm_bf16s<false><<<dim3(cdiv(CN, 128), cdiv(T_, 64), B_), 256, SMEM>>>(
        Yh, Yl, (size_t)CN * HP2, Hh, Hl, (size_t)T_ * HP2,
        L, nullptr, nullptr, (size_t)CN * T_, CN, T_, HD, scale);

    // 4+5) softmax + sparse gather -> out
    softmax_gather<<<dim3(CN, B_), 256>>>(H, out);
}

// round 12
// speedup vs baseline: 1.6512x; 1.0302x over previous
#include <cuda_runtime.h>
#include <cuda_bf16.h>
#include <math_constants.h>
#include <cstdint>

#define B_  64
#define T_  1380
#define TP  1408        // T padded to multiple of 32
#define TP2 (TP/2)      // 704 packed pairs
#define XD  96
#define XP2 (XD/2)      // 48
#define HD  192
#define HP2 (HD/2)      // 96
#define CN  345

#define THR_LN 18.421f   // -ln(1e-8): dropped mass <= T*1e-8 = 1.38e-5

// ---------------------------------------------------------------------------
// Scratch (device globals). hi/lo bf16 pairs packed in uint32 (low = lower k).
// ---------------------------------------------------------------------------
__device__ uint32_t g_W2h[(size_t)CN * TP2],      g_W2l[(size_t)CN * TP2];
__device__ uint32_t g_Xth[(size_t)B_ * XD * TP2], g_Xtl[(size_t)B_ * XD * TP2];
__device__ uint32_t g_W1th[(size_t)HD * XP2],     g_W1tl[(size_t)HD * XP2];
__device__ uint32_t g_Hh [(size_t)B_ * T_ * HP2], g_Hl [(size_t)B_ * T_ * HP2];
__device__ uint32_t g_Zh [(size_t)B_ * CN * XP2], g_Zl [(size_t)B_ * CN * XP2];
__device__ uint32_t g_Yh [(size_t)B_ * CN * HP2], g_Yl [(size_t)B_ * CN * HP2];
__device__ float    g_L  [(size_t)B_ * CN * T_];
__device__ uint32_t g_Mx [(size_t)B_ * CN];      // ordered-uint row max

// ---------------------------------------------------------------------------
// Helpers
// ---------------------------------------------------------------------------
__device__ __forceinline__ uint32_t enc_f(float f) {
    uint32_t u = __float_as_uint(f);
    return (u & 0x80000000u) ? ~u : (u | 0x80000000u);
}
__device__ __forceinline__ float dec_f(uint32_t k) {
    uint32_t u = (k & 0x80000000u) ? (k ^ 0x80000000u) : ~k;
    return __uint_as_float(u);
}

__device__ __forceinline__ void split_pair(float x0, float x1,
                                           uint32_t& hi, uint32_t& lo) {
    __nv_bfloat16 h0 = __float2bfloat16_rn(x0);
    __nv_bfloat16 h1 = __float2bfloat16_rn(x1);
    float r0 = x0 - __bfloat162float(h0);
    float r1 = x1 - __bfloat162float(h1);
    __nv_bfloat16 l0 = __float2bfloat16_rn(r0);
    __nv_bfloat16 l1 = __float2bfloat16_rn(r1);
    hi = ((uint32_t)__bfloat16_as_ushort(h1) << 16) | __bfloat16_as_ushort(h0);
    lo = ((uint32_t)__bfloat16_as_ushort(l1) << 16) | __bfloat16_as_ushort(l0);
}

__device__ __forceinline__ void mma_bf16(float* c, const uint32_t* a, const uint32_t* b) {
    asm volatile(
        "mma.sync.aligned.m16n8k16.row.col.f32.bf16.bf16.f32 "
        "{%0,%1,%2,%3}, {%4,%5,%6,%7}, {%8,%9}, {%0,%1,%2,%3};"
        : "+f"(c[0]), "+f"(c[1]), "+f"(c[2]), "+f"(c[3])
        : "r"(a[0]), "r"(a[1]), "r"(a[2]), "r"(a[3]),
          "r"(b[0]), "r"(b[1]));
}

__device__ __forceinline__ void ldsm4(uint32_t* r, uint32_t saddr) {
    asm volatile("ldmatrix.sync.aligned.m8n8.x4.shared.b16 {%0,%1,%2,%3}, [%4];"
                 : "=r"(r[0]), "=r"(r[1]), "=r"(r[2]), "=r"(r[3]) : "r"(saddr));
}

__device__ __forceinline__ void cp16(uint32_t dst, const void* src, bool ok) {
    asm volatile(
        "{\n\t.reg .pred p;\n\t.reg .b32 sz;\n\t"
        "setp.ne.u32 p, %2, 0;\n\t"
        "selp.b32 sz, 16, 0, p;\n\t"
        "cp.async.cg.shared.global [%0], [%1], 16, sz;\n\t}"
        :: "r"(dst), "l"(src), "r"((uint32_t)ok) : "memory");
}
#define CP_COMMIT() asm volatile("cp.async.commit_group;" ::: "memory")

// ---------------------------------------------------------------------------
// Prepass: elementwise split+pack (zero-pad cols to Cp2 pairs)
// ---------------------------------------------------------------------------
__global__ void split_pack(const float* __restrict__ src,
                           uint32_t* __restrict__ dh, uint32_t* __restrict__ dl,
                           int rows, int C, int Cp2) {
    size_t idx = (size_t)blockIdx.x * 256 + threadIdx.x;
    size_t total = (size_t)rows * Cp2;
    if (idx >= total) return;
    int r = (int)(idx / Cp2);
    int j = (int)(idx - (size_t)r * Cp2);
    float2 v = make_float2(0.f, 0.f);
    if (2 * j < C)
        v = *reinterpret_cast<const float2*>(src + (size_t)r * C + 2 * j);
    uint32_t hi, lo;
    split_pair(v.x, v.y, hi, lo);
    dh[idx] = hi;
    dl[idx] = lo;
}

// ---------------------------------------------------------------------------
// Prepass: split + transpose + pack.  src [b][R][C] -> [b][C][Rp2]
// ---------------------------------------------------------------------------
__global__ void split_transpose(const float* __restrict__ src, size_t sSrc,
                                uint32_t* __restrict__ dh, uint32_t* __restrict__ dl,
                                size_t sDst, int R, int C, int Rp2) {
    __shared__ float t[32][33];
    const int b = blockIdx.z;
    src += sSrc * b;
    dh  += sDst * b;
    dl  += sDst * b;
    const int r0 = blockIdx.x * 32;
    const int c0 = blockIdx.y * 32;
    const int tx = threadIdx.x, ty = threadIdx.y;

    #pragma unroll
    for (int i = 0; i < 4; i++) {
        int r = r0 + ty + i * 8, c = c0 + tx;
        t[ty + i * 8][tx] = (r < R && c < C) ? src[(size_t)r * C + c] : 0.f;
    }
    __syncthreads();
    if (tx < 16) {
        #pragma unroll
        for (int i = 0; i < 4; i++) {
            int cc = ty + i * 8, c = c0 + cc;
            if (c < C) {
                uint32_t hi, lo;
                split_pair(t[2 * tx][cc], t[2 * tx + 1][cc], hi, lo);
                size_t o = (size_t)c * Rp2 + (r0 >> 1) + tx;
                dh[o] = hi;
                dl[o] = lo;
            }
        }
    }
}

// ---------------------------------------------------------------------------
// Init row-max array (ordered-uint 0 == very small)
// ---------------------------------------------------------------------------
__global__ void init_max() {
    int i = blockIdx.x * 256 + threadIdx.x;
    if (i < B_ * CN) g_Mx[i] = 0u;
}

// ---------------------------------------------------------------------------
// bf16 split-compensated tensor-core GEMM (NT, packed hi/lo operands).
//   C[b] = alpha * A[b] (M x Kp) @ B[b] (N x Kp)^T,  products hh+hl+lh
// BM=128, BN templated (96), BK=32, 256 threads (8 warps 4x2),
// warp tile 32 x BN/2. 4-stage cp.async pipeline, XOR-swizzled pitch-16 smem.
// Stage (u32): Ah[0,2048) Al[2048,4096) Bh[4096,4096+16BN) Bl[...+16BN)
// WMAX: deterministic atomicMax of each output row into Mx (ordered-uint).
// ---------------------------------------------------------------------------
template<int BN, bool OSPLIT, bool WMAX>
__global__ __launch_bounds__(256, 2)
void gemm_bf16s(const uint32_t* __restrict__ Ah, const uint32_t* __restrict__ Al, size_t sA,
                const uint32_t* __restrict__ Bh, const uint32_t* __restrict__ Bl, size_t sB,
                float* __restrict__ Cf, uint32_t* __restrict__ Ch, uint32_t* __restrict__ Cl,
                uint32_t* __restrict__ Mx,
                size_t sC, int M, int N, int Kp, float alpha)
{
    constexpr int NI = BN / 16;                // 8-col subtiles per warp
    constexpr int PR = BN / 32;                // 16-row ldsm chunks per warp
    constexpr int B_U32   = BN * 16 * 2;
    constexpr int STG_U32 = 4096 + B_U32;
    constexpr int STG_B   = STG_U32 * 4;
    constexpr int NSTAGE  = 4;

    extern __shared__ uint32_t sm[];
    const uint32_t sbase = (uint32_t)__cvta_generic_to_shared(sm);

    const int b = blockIdx.z;
    Ah += sA * b;  Al += sA * b;
    Bh += sB * b;  Bl += sB * b;
    const int m0 = blockIdx.x * 128;
    const int n0 = blockIdx.y * BN;
    const int tid  = threadIdx.x;
    const int warp = tid >> 5, lane = tid & 31;
    const int wm = warp >> 1, wn = warp & 1;       // 4 x 2 warp grid
    const int l4 = lane >> 2, lk = lane & 3;
    const int Kp2 = Kp >> 1;

    // per-lane ldmatrix addresses (stage 0, kk=0, hi arrays), bytes
    const int lt = lane >> 3, lr = lane & 7;
    const int rowA = (lt & 1) * 8 + lr;
    const int gA   = lt >> 1;
    const int rowB = (lt >> 1) * 8 + lr;
    const int gB   = lt & 1;

    uint32_t aAddr[2], bAddr[PR];
    #pragma unroll
    for (int mi = 0; mi < 2; mi++) {
        int r = wm * 32 + mi * 16 + rowA;
        int sw = (r >> 1) & 3;
        aAddr[mi] = (uint32_t)((r * 16 + ((gA ^ sw) * 4)) << 2);
    }
    #pragma unroll
    for (int pr = 0; pr < PR; pr++) {
        int r = wn * (BN / 2) + pr * 16 + rowB;
        int sw = (r >> 1) & 3;
        bAddr[pr] = (uint32_t)((4096 + r * 16 + ((gB ^ sw) * 4)) << 2);
    }

    float acc[2][NI][4] = {};
    const int nck = Kp >> 5;

    auto load_tile = [&](int ck, int st) {
        const uint32_t stg = sbase + (uint32_t)(st * STG_B);
        const int k0 = ck * 16;
        #pragma unroll
        for (int i = 0; i < 4; i++) {              // A: 1024 chunks
            int idx = tid + i * 256;
            int arr = idx >> 9, rem = idx & 511;
            int r = rem >> 2, c4 = rem & 3;
            int sw = c4 ^ ((r >> 1) & 3);
            int gm = m0 + r;
            bool ok = gm < M;
            const uint32_t* base = arr ? Al : Ah;
            const uint32_t* src = ok ? (base + (size_t)gm * Kp2 + k0 + c4 * 4) : base;
            cp16(stg + ((arr * 2048 + r * 16 + sw * 4) << 2), src, ok);
        }
        #pragma unroll
        for (int i = 0; i < BN / 32; i++) {        // B: 8*BN chunks
            int idx = tid + i * 256;
            int arr = idx / (4 * BN);
            int rem = idx - arr * 4 * BN;
            int r = rem >> 2, c4 = rem & 3;
            int sw = c4 ^ ((r >> 1) & 3);
            int gn = n0 + r;
            bool ok = gn < N;
            const uint32_t* base = arr ? Bl : Bh;
            const uint32_t* src = ok ? (base + (size_t)gn * Kp2 + k0 + c4 * 4) : base;
            cp16(stg + ((4096 + arr * (BN * 16) + r * 16 + sw * 4) << 2), src, ok);
        }
    };

    #pragma unroll
    for (int p = 0; p < NSTAGE - 1; p++) {
        if (p < nck) load_tile(p, p);
        CP_COMMIT();
    }

    for (int ck = 0; ck < nck; ck++) {
        asm volatile("cp.async.wait_group %0;" :: "n"(NSTAGE - 2) : "memory");
        __syncthreads();

        if (ck + NSTAGE - 1 < nck) load_tile(ck + NSTAGE - 1, (ck + NSTAGE - 1) & 3);
        CP_COMMIT();

        const uint32_t stg = sbase + (uint32_t)((ck & 3) * STG_B);

        #pragma unroll
        for (int kk = 0; kk < 2; kk++) {
            const uint32_t kx = kk ? 32u : 0u;
            uint32_t a_h[2][4], a_l[2][4], b_h[NI][2], b_l[NI][2];
            #pragma unroll
            for (int mi = 0; mi < 2; mi++) {
                uint32_t ad = (stg + aAddr[mi]) ^ kx;
                ldsm4(a_h[mi], ad);
                ldsm4(a_l[mi], ad + 8192);
            }
            #pragma unroll
            for (int pr = 0; pr < PR; pr++) {
                uint32_t bd = (stg + bAddr[pr]) ^ kx;
                uint32_t bt[4];
                ldsm4(bt, bd);
                b_h[2 * pr][0] = bt[0]; b_h[2 * pr][1] = bt[1];
                b_h[2 * pr + 1][0] = bt[2]; b_h[2 * pr + 1][1] = bt[3];
                ldsm4(bt, bd + (uint32_t)(B_U32 / 2 * 4));
                b_l[2 * pr][0] = bt[0]; b_l[2 * pr][1] = bt[1];
                b_l[2 * pr + 1][0] = bt[2]; b_l[2 * pr + 1][1] = bt[3];
            }
            #pragma unroll
            for (int mi = 0; mi < 2; mi++)
                #pragma unroll
                for (int ni = 0; ni < NI; ni++) {
                    mma_bf16(acc[mi][ni], a_h[mi], b_h[ni]);
                    mma_bf16(acc[mi][ni], a_h[mi], b_l[ni]);
                    mma_bf16(acc[mi][ni], a_l[mi], b_h[ni]);
                }
        }
    }

    // ---- epilogue ----
    const int N2 = N >> 1;
    #pragma unroll
    for (int mi = 0; mi < 2; mi++) {
        int r0 = m0 + wm * 32 + mi * 16 + l4;
        float mx0 = -CUDART_INF_F, mx1 = -CUDART_INF_F;
        #pragma unroll
        for (int ni = 0; ni < NI; ni++) {
            int c0 = n0 + wn * (BN / 2) + ni * 8 + 2 * lk;
            if (c0 < N) {
                float v0 = alpha * acc[mi][ni][0], v1 = alpha * acc[mi][ni][1];
                float v2 = alpha * acc[mi][ni][2], v3 = alpha * acc[mi][ni][3];
                if (OSPLIT) {
                    int pj = c0 >> 1;
                    if (r0 < M) {
                        uint32_t hi, lo;
                        split_pair(v0, v1, hi, lo);
                        Ch[sC * b + (size_t)r0 * N2 + pj] = hi;
                        Cl[sC * b + (size_t)r0 * N2 + pj] = lo;
                    }
                    if (r0 + 8 < M) {
                        uint32_t hi, lo;
                        split_pair(v2, v3, hi, lo);
                        Ch[sC * b + (size_t)(r0 + 8) * N2 + pj] = hi;
                        Cl[sC * b + (size_t)(r0 + 8) * N2 + pj] = lo;
                    }
                } else {
                    if (r0 < M)
                        *reinterpret_cast<float2*>(Cf + sC * b + (size_t)r0 * N + c0)
                            = make_float2(v0, v1);
                    if (r0 + 8 < M)
                        *reinterpret_cast<float2*>(Cf + sC * b + (size_t)(r0 + 8) * N + c0)
                            = make_float2(v2, v3);
                }
                if (WMAX) {
                    mx0 = fmaxf(mx0, fmaxf(v0, v1));
                    mx1 = fmaxf(mx1, fmaxf(v2, v3));
                }
            }
        }
        if (WMAX) {
            #pragma unroll
            for (int o = 1; o <= 2; o <<= 1) {
                mx0 = fmaxf(mx0, __shfl_xor_sync(0xffffffffu, mx0, o));
                mx1 = fmaxf(mx1, __shfl_xor_sync(0xffffffffu, mx1, o));
            }
            if (lk == 0 && mx0 > -CUDART_INF_F) {
                if (r0 < M)     atomicMax(&Mx[(size_t)b * M + r0], enc_f(mx0));
                if (r0 + 8 < M) atomicMax(&Mx[(size_t)b * M + r0 + 8], enc_f(mx1));
            }
        }
    }
}

// ---------------------------------------------------------------------------
// Sparse softmax-gather, single pass over L.
// Row max is exact (from g_Mx). Keep logits > max - THR_LN; normalize by the
// kept-set sum (dropped mass <= 1.38e-5). Deterministic: ballot-ordered
// per-warp compaction + fixed concat order + fixed-order sums.
// ---------------------------------------------------------------------------
#define SEG 173          // ceil(1380/8)
#define CAP 176

__global__ void softmax_gather(const float* __restrict__ H,
                               float* __restrict__ out) {
    const int c = blockIdx.x, b = blockIdx.y;
    const size_t row = (size_t)b * CN + c;
    const float* Lr = g_L + row * T_;
    const int tid = threadIdx.x;
    const int lane = tid & 31, warp = tid >> 5;

    const float M = dec_f(g_Mx[row]);
    const float thr = M - THR_LN;

    __shared__ uint32_t sidx[8 * CAP];
    __shared__ float    slog[8 * CAP];
    __shared__ int      cnt[8];
    __shared__ int      off[9];
    __shared__ float    sinv;
    __shared__ uint32_t fidx[T_];
    __shared__ float    fp[T_];

    // 1) parallel ordered compaction on raw logits (one pass over L)
    {
        int s0 = warp * SEG;
        int s1 = min(s0 + SEG, T_);
        int base = 0;
        for (int i0 = s0; i0 < s1; i0 += 32) {
            int i = i0 + lane;
            float l = (i < s1) ? Lr[i] : -CUDART_INF_F;
            bool k = l > thr;
            unsigned bal = __ballot_sync(0xffffffffu, k);
            int o = __popc(bal & ((1u << lane) - 1u));
            if (k) {
                sidx[warp * CAP + base + o] = (uint32_t)i;
                slog[warp * CAP + base + o] = l;
            }
            base += __popc(bal);
        }
        if (lane == 0) cnt[warp] = base;
    }
    __syncthreads();

    // 2) offsets + kept-set sum (thread 0, fixed order -> deterministic)
    if (tid == 0) {
        int t = 0;
        #pragma unroll
        for (int w = 0; w < 8; w++) { off[w] = t; t += cnt[w]; }
        off[8] = t;
        float S = 0.f;
        for (int w = 0; w < 8; w++)
            for (int j = 0; j < cnt[w]; j++)
                S += __expf(slog[w * CAP + j] - M);
        sinv = __frcp_rn(S);
    }
    __syncthreads();

    // 3) flatten + probabilities
    {
        float inv = sinv;
        int n = cnt[warp], o = off[warp];
        for (int j = lane; j < n; j += 32) {
            fidx[o + j] = sidx[warp * CAP + j];
            fp[o + j]   = __expf(slog[warp * CAP + j] - M) * inv;
        }
    }
    __syncthreads();

    // 4) gather output row (fixed order)
    const int n = off[8];
    const float* Hb = H + (size_t)b * T_ * HD;
    float* Orow = out + row * HD;
    for (int j = tid; j < HD; j += 256) {
        float a = 0.f;
        for (int k = 0; k < n; k++)
            a += fp[k] * Hb[(size_t)fidx[k] * HD + j];
        Orow[j] = a;
    }
}

// ---------------------------------------------------------------------------

static inline int cdiv(int a, int b) { return (a + b - 1) / b; }

extern "C" void kernel_launch(void* const* d_in, const int* in_sizes, int n_in,
                              void* d_out, int out_size) {
    const float* X  = (const float*)d_in[0];  // [B,T,XD]
    const float* H  = (const float*)d_in[1];  // [B,T,HD]
    const float* W1 = (const float*)d_in[2];  // [XD,HD]
    const float* W2 = (const float*)d_in[3];  // [CN,T]
    float* out = (float*)d_out;               // [B,CN,HD]

    uint32_t *W2h, *W2l, *Xth, *Xtl, *W1th, *W1tl, *Hh, *Hl;
    uint32_t *Zh, *Zl, *Yh, *Yl, *Mx;
    float* L;
    cudaGetSymbolAddress((void**)&W2h, g_W2h);  cudaGetSymbolAddress((void**)&W2l, g_W2l);
    cudaGetSymbolAddress((void**)&Xth, g_Xth);  cudaGetSymbolAddress((void**)&Xtl, g_Xtl);
    cudaGetSymbolAddress((void**)&W1th, g_W1th); cudaGetSymbolAddress((void**)&W1tl, g_W1tl);
    cudaGetSymbolAddress((void**)&Hh, g_Hh);    cudaGetSymbolAddress((void**)&Hl, g_Hl);
    cudaGetSymbolAddress((void**)&Zh, g_Zh);    cudaGetSymbolAddress((void**)&Zl, g_Zl);
    cudaGetSymbolAddress((void**)&Yh, g_Yh);    cudaGetSymbolAddress((void**)&Yl, g_Yl);
    cudaGetSymbolAddress((void**)&Mx, g_Mx);
    cudaGetSymbolAddress((void**)&L,  g_L);

    const float scale = 1.0f / sqrtf((float)XD * (float)HD);

    constexpr int SMEM = 4 * (4096 + 96 * 32) * 4;   // 4 stages x 28672 B = 114688

    static bool attr_done = false;
    if (!attr_done) {
        cudaFuncSetAttribute(gemm_bf16s<96, true, false>,
            cudaFuncAttributeMaxDynamicSharedMemorySize, SMEM);
        cudaFuncSetAttribute(gemm_bf16s<96, false, true>,
            cudaFuncAttributeMaxDynamicSharedMemorySize, SMEM);
        attr_done = true;
    }

    // ---- prepass ----
    init_max<<<cdiv(B_ * CN, 256), 256>>>();
    {
        size_t tot = (size_t)CN * TP2;
        split_pack<<<(int)cdiv((int)tot, 256), 256>>>(W2, W2h, W2l, CN, T_, TP2);
    }
    {
        size_t tot = (size_t)B_ * T_ * HP2;
        split_pack<<<(int)((tot + 255) / 256), 256>>>(H, Hh, Hl, B_ * T_, HD, HP2);
    }
    split_transpose<<<dim3(TP / 32, cdiv(XD, 32), B_), dim3(32, 8)>>>(
        X, (size_t)T_ * XD, Xth, Xtl, (size_t)XD * TP2, T_, XD, TP2);
    split_transpose<<<dim3(XD / 32, cdiv(HD, 32), 1), dim3(32, 8)>>>(
        W1, 0, W1th, W1tl, 0, XD, HD, XP2);

    // 1) Z[b] = W2 @ X[b]    A=W2 [CN,TP], B=Xt [XD,TP] -> Z split [CN,XP2]
    gemm_bf16s<96, true, false><<<dim3(cdiv(CN, 128), cdiv(XD, 96), B_), 256, SMEM>>>(
        W2h, W2l, 0, Xth, Xtl, (size_t)XD * TP2,
        nullptr, Zh, Zl, nullptr, (size_t)CN * XP2, CN, XD, TP, 1.0f);

    // 2) Y[b] = Z[b] @ W1    A=Z [CN,XD], B=W1t [HD,XD] -> Y split [CN,HP2]
    gemm_bf16s<96, true, false><<<dim3(cdiv(CN, 128), cdiv(HD, 96), B_), 256, SMEM>>>(
        Zh, Zl, (size_t)CN * XP2, W1th, W1tl, 0,
        nullptr, Yh, Yl, nullptr, (size_t)CN * HP2, CN, HD, XD, 1.0f);

    // 3) L[b] = scale * Y[b] @ H[b]^T  (+ deterministic row max -> g_Mx)
    gemm_bf16s<96, false, true><<<dim3(cdiv(CN, 128), cdiv(T_, 96), B_), 256, SMEM>>>(
        Yh, Yl, (size_t)CN * HP2, Hh, Hl, (size_t)T_ * HP2,
        L, nullptr, nullptr, Mx, (size_t)CN * T_, CN, T_, HD, scale);

    // 4+5) single-pass sparse softmax-gather -> out
    softmax_gather<<<dim3(CN, B_), 256>>>(H, out);
}

// round 13
// speedup vs baseline: 1.6870x; 1.0217x over previous
#include <cuda_runtime.h>
#include <cuda_bf16.h>
#include <math_constants.h>
#include <cstdint>

#define B_  64
#define T_  1380
#define T2  (T_/2)      // 690 bf16 pairs per L row
#define TP  1408        // T padded to multiple of 32
#define TP2 (TP/2)      // 704 packed pairs
#define XD  96
#define XP2 (XD/2)      // 48
#define HD  192
#define HP2 (HD/2)      // 96
#define CN  345

#define THR_LN   18.421f   // -ln(1e-8)
#define SLACK    2.0f      // covers bf16-product + bf16-storage logit error (bound ~1.0)

// ---------------------------------------------------------------------------
// Scratch (device globals). hi/lo bf16 pairs packed in uint32 (low = lower k).
// ---------------------------------------------------------------------------
__device__ uint32_t g_W2h[(size_t)CN * TP2],      g_W2l[(size_t)CN * TP2];
__device__ uint32_t g_Xth[(size_t)B_ * XD * TP2], g_Xtl[(size_t)B_ * XD * TP2];
__device__ uint32_t g_W1th[(size_t)HD * XP2],     g_W1tl[(size_t)HD * XP2];
__device__ uint32_t g_Hh [(size_t)B_ * T_ * HP2];
__device__ uint32_t g_Zh [(size_t)B_ * CN * XP2], g_Zl [(size_t)B_ * CN * XP2];
__device__ uint32_t g_Yh [(size_t)B_ * CN * HP2], g_Yl [(size_t)B_ * CN * HP2];
__device__ uint32_t g_Lb [(size_t)B_ * CN * T2];  // bf16x2 packed logits
__device__ uint32_t g_Mx [(size_t)B_ * CN];       // ordered-uint row max (of stored bf16)

// ---------------------------------------------------------------------------
// Helpers
// ---------------------------------------------------------------------------
__device__ __forceinline__ uint32_t enc_f(float f) {
    uint32_t u = __float_as_uint(f);
    return (u & 0x80000000u) ? ~u : (u | 0x80000000u);
}
__device__ __forceinline__ float dec_f(uint32_t k) {
    uint32_t u = (k & 0x80000000u) ? (k ^ 0x80000000u) : ~k;
    return __uint_as_float(u);
}

__device__ __forceinline__ void split_pair(float x0, float x1,
                                           uint32_t& hi, uint32_t& lo) {
    __nv_bfloat16 h0 = __float2bfloat16_rn(x0);
    __nv_bfloat16 h1 = __float2bfloat16_rn(x1);
    float r0 = x0 - __bfloat162float(h0);
    float r1 = x1 - __bfloat162float(h1);
    __nv_bfloat16 l0 = __float2bfloat16_rn(r0);
    __nv_bfloat16 l1 = __float2bfloat16_rn(r1);
    hi = ((uint32_t)__bfloat16_as_ushort(h1) << 16) | __bfloat16_as_ushort(h0);
    lo = ((uint32_t)__bfloat16_as_ushort(l1) << 16) | __bfloat16_as_ushort(l0);
}

__device__ __forceinline__ float bf_lo(uint32_t u) {
    return __bfloat162float(__ushort_as_bfloat16((unsigned short)(u & 0xffffu)));
}
__device__ __forceinline__ float bf_hi(uint32_t u) {
    return __bfloat162float(__ushort_as_bfloat16((unsigned short)(u >> 16)));
}

__device__ __forceinline__ void mma_bf16(float* c, const uint32_t* a, const uint32_t* b) {
    asm volatile(
        "mma.sync.aligned.m16n8k16.row.col.f32.bf16.bf16.f32 "
        "{%0,%1,%2,%3}, {%4,%5,%6,%7}, {%8,%9}, {%0,%1,%2,%3};"
        : "+f"(c[0]), "+f"(c[1]), "+f"(c[2]), "+f"(c[3])
        : "r"(a[0]), "r"(a[1]), "r"(a[2]), "r"(a[3]),
          "r"(b[0]), "r"(b[1]));
}

__device__ __forceinline__ void ldsm4(uint32_t* r, uint32_t saddr) {
    asm volatile("ldmatrix.sync.aligned.m8n8.x4.shared.b16 {%0,%1,%2,%3}, [%4];"
                 : "=r"(r[0]), "=r"(r[1]), "=r"(r[2]), "=r"(r[3]) : "r"(saddr));
}

__device__ __forceinline__ void cp16(uint32_t dst, const void* src, bool ok) {
    asm volatile(
        "{\n\t.reg .pred p;\n\t.reg .b32 sz;\n\t"
        "setp.ne.u32 p, %2, 0;\n\t"
        "selp.b32 sz, 16, 0, p;\n\t"
        "cp.async.cg.shared.global [%0], [%1], 16, sz;\n\t}"
        :: "r"(dst), "l"(src), "r"((uint32_t)ok) : "memory");
}
#define CP_COMMIT() asm volatile("cp.async.commit_group;" ::: "memory")

// ---------------------------------------------------------------------------
// Prepass kernels
// ---------------------------------------------------------------------------
__global__ void split_pack(const float* __restrict__ src,
                           uint32_t* __restrict__ dh, uint32_t* __restrict__ dl,
                           int rows, int C, int Cp2) {
    size_t idx = (size_t)blockIdx.x * 256 + threadIdx.x;
    size_t total = (size_t)rows * Cp2;
    if (idx >= total) return;
    int r = (int)(idx / Cp2);
    int j = (int)(idx - (size_t)r * Cp2);
    float2 v = make_float2(0.f, 0.f);
    if (2 * j < C)
        v = *reinterpret_cast<const float2*>(src + (size_t)r * C + 2 * j);
    uint32_t hi, lo;
    split_pair(v.x, v.y, hi, lo);
    dh[idx] = hi;
    dl[idx] = lo;
}

__global__ void pack_hi(const float* __restrict__ src,
                        uint32_t* __restrict__ dh, int rows, int C, int Cp2) {
    size_t idx = (size_t)blockIdx.x * 256 + threadIdx.x;
    size_t total = (size_t)rows * Cp2;
    if (idx >= total) return;
    int r = (int)(idx / Cp2);
    int j = (int)(idx - (size_t)r * Cp2);
    float2 v = make_float2(0.f, 0.f);
    if (2 * j < C)
        v = *reinterpret_cast<const float2*>(src + (size_t)r * C + 2 * j);
    __nv_bfloat16 h0 = __float2bfloat16_rn(v.x);
    __nv_bfloat16 h1 = __float2bfloat16_rn(v.y);
    dh[idx] = ((uint32_t)__bfloat16_as_ushort(h1) << 16) | __bfloat16_as_ushort(h0);
}

__global__ void split_transpose(const float* __restrict__ src, size_t sSrc,
                                uint32_t* __restrict__ dh, uint32_t* __restrict__ dl,
                                size_t sDst, int R, int C, int Rp2) {
    __shared__ float t[32][33];
    const int b = blockIdx.z;
    src += sSrc * b;
    dh  += sDst * b;
    dl  += sDst * b;
    const int r0 = blockIdx.x * 32;
    const int c0 = blockIdx.y * 32;
    const int tx = threadIdx.x, ty = threadIdx.y;

    #pragma unroll
    for (int i = 0; i < 4; i++) {
        int r = r0 + ty + i * 8, c = c0 + tx;
        t[ty + i * 8][tx] = (r < R && c < C) ? src[(size_t)r * C + c] : 0.f;
    }
    __syncthreads();
    if (tx < 16) {
        #pragma unroll
        for (int i = 0; i < 4; i++) {
            int cc = ty + i * 8, c = c0 + cc;
            if (c < C) {
                uint32_t hi, lo;
                split_pair(t[2 * tx][cc], t[2 * tx + 1][cc], hi, lo);
                size_t o = (size_t)c * Rp2 + (r0 >> 1) + tx;
                dh[o] = hi;
                dl[o] = lo;
            }
        }
    }
}

__global__ void init_max() {
    int i = blockIdx.x * 256 + threadIdx.x;
    if (i < B_ * CN) g_Mx[i] = 0u;
}

// ---------------------------------------------------------------------------
// bf16 tensor-core GEMM (NT, packed bf16-pair operands).
//   C[b] = alpha * A[b] (M x Kp) @ B[b] (N x Kp)^T
// PROD==3: split-compensated (hh+hl+lh), PROD==1: hi*hi only.
// MODE==1: write split Ch/Cl; MODE==2: write packed-bf16 Ch + atomicMax Mx.
// BM=128, BN templated, BK=32, 256 threads (8 warps 4x2), warp tile 32 x BN/2.
// 4-stage cp.async pipeline, XOR-swizzled pitch-16 smem.
// ---------------------------------------------------------------------------
template<int BN, int MODE, int PROD>
__global__ __launch_bounds__(256, 2)
void gemm_bf16s(const uint32_t* __restrict__ Ah, const uint32_t* __restrict__ Al, size_t sA,
                const uint32_t* __restrict__ Bh, const uint32_t* __restrict__ Bl, size_t sB,
                uint32_t* __restrict__ Ch, uint32_t* __restrict__ Cl,
                uint32_t* __restrict__ Mx,
                size_t sC, int M, int N, int Kp, float alpha)
{
    constexpr int NI = BN / 16;
    constexpr int PR = BN / 32;
    constexpr int NARR = (PROD == 3) ? 2 : 1;
    constexpr int A_U32 = 2048 * NARR;
    constexpr int B_OFF = A_U32;                 // u32 offset of B-hi
    constexpr int B_U32 = BN * 16 * NARR;
    constexpr int STG_U32 = A_U32 + B_U32;
    constexpr int STG_B = STG_U32 * 4;
    constexpr int NSTAGE = 4;
    constexpr int TA = NARR * 512;               // A 16B-chunks per stage
    constexpr int TB = NARR * BN * 4;            // B 16B-chunks per stage

    extern __shared__ uint32_t sm[];
    const uint32_t sbase = (uint32_t)__cvta_generic_to_shared(sm);

    const int b = blockIdx.z;
    Ah += sA * b;  Al += sA * b;
    Bh += sB * b;  Bl += sB * b;
    const int m0 = blockIdx.x * 128;
    const int n0 = blockIdx.y * BN;
    const int tid  = threadIdx.x;
    const int warp = tid >> 5, lane = tid & 31;
    const int wm = warp >> 1, wn = warp & 1;
    const int l4 = lane >> 2, lk = lane & 3;
    const int Kp2 = Kp >> 1;

    const int lt = lane >> 3, lr = lane & 7;
    const int rowA = (lt & 1) * 8 + lr;
    const int gA   = lt >> 1;
    const int rowB = (lt >> 1) * 8 + lr;
    const int gB   = lt & 1;

    uint32_t aAddr[2], bAddr[PR];
    #pragma unroll
    for (int mi = 0; mi < 2; mi++) {
        int r = wm * 32 + mi * 16 + rowA;
        int sw = (r >> 1) & 3;
        aAddr[mi] = (uint32_t)((r * 16 + ((gA ^ sw) * 4)) << 2);
    }
    #pragma unroll
    for (int pr = 0; pr < PR; pr++) {
        int r = wn * (BN / 2) + pr * 16 + rowB;
        int sw = (r >> 1) & 3;
        bAddr[pr] = (uint32_t)((B_OFF + r * 16 + ((gB ^ sw) * 4)) << 2);
    }

    float acc[2][NI][4] = {};
    const int nck = Kp >> 5;

    auto load_tile = [&](int ck, int st) {
        const uint32_t stg = sbase + (uint32_t)(st * STG_B);
        const int k0 = ck * 16;
        #pragma unroll
        for (int i = 0; i < (TA + 255) / 256; i++) {
            int idx = tid + i * 256;
            if (TA % 256 == 0 || idx < TA) {
                int arr = idx >> 9, rem = idx & 511;
                int r = rem >> 2, c4 = rem & 3;
                int sw = c4 ^ ((r >> 1) & 3);
                int gm = m0 + r;
                bool ok = gm < M;
                const uint32_t* base = arr ? Al : Ah;
                const uint32_t* src = ok ? (base + (size_t)gm * Kp2 + k0 + c4 * 4) : base;
                cp16(stg + ((arr * 2048 + r * 16 + sw * 4) << 2), src, ok);
            }
        }
        #pragma unroll
        for (int i = 0; i < (TB + 255) / 256; i++) {
            int idx = tid + i * 256;
            if (TB % 256 == 0 || idx < TB) {
                int arr = idx / (4 * BN);
                int rem = idx - arr * 4 * BN;
                int r = rem >> 2, c4 = rem & 3;
                int sw = c4 ^ ((r >> 1) & 3);
                int gn = n0 + r;
                bool ok = gn < N;
                const uint32_t* base = arr ? Bl : Bh;
                const uint32_t* src = ok ? (base + (size_t)gn * Kp2 + k0 + c4 * 4) : base;
                cp16(stg + ((B_OFF + arr * (BN * 16) + r * 16 + sw * 4) << 2), src, ok);
            }
        }
    };

    #pragma unroll
    for (int p = 0; p < NSTAGE - 1; p++) {
        if (p < nck) load_tile(p, p);
        CP_COMMIT();
    }

    for (int ck = 0; ck < nck; ck++) {
        asm volatile("cp.async.wait_group %0;" :: "n"(NSTAGE - 2) : "memory");
        __syncthreads();

        if (ck + NSTAGE - 1 < nck) load_tile(ck + NSTAGE - 1, (ck + NSTAGE - 1) & 3);
        CP_COMMIT();

        const uint32_t stg = sbase + (uint32_t)((ck & 3) * STG_B);

        #pragma unroll
        for (int kk = 0; kk < 2; kk++) {
            const uint32_t kx = kk ? 32u : 0u;
            uint32_t a_h[2][4], a_l[2][4], b_h[NI][2], b_l[NI][2];
            #pragma unroll
            for (int mi = 0; mi < 2; mi++) {
                uint32_t ad = (stg + aAddr[mi]) ^ kx;
                ldsm4(a_h[mi], ad);
                if (PROD == 3) ldsm4(a_l[mi], ad + 8192);
            }
            #pragma unroll
            for (int pr = 0; pr < PR; pr++) {
                uint32_t bd = (stg + bAddr[pr]) ^ kx;
                uint32_t bt[4];
                ldsm4(bt, bd);
                b_h[2 * pr][0] = bt[0]; b_h[2 * pr][1] = bt[1];
                b_h[2 * pr + 1][0] = bt[2]; b_h[2 * pr + 1][1] = bt[3];
                if (PROD == 3) {
                    ldsm4(bt, bd + (uint32_t)(BN * 16 * 4));
                    b_l[2 * pr][0] = bt[0]; b_l[2 * pr][1] = bt[1];
                    b_l[2 * pr + 1][0] = bt[2]; b_l[2 * pr + 1][1] = bt[3];
                }
            }
            #pragma unroll
            for (int mi = 0; mi < 2; mi++)
                #pragma unroll
                for (int ni = 0; ni < NI; ni++) {
                    mma_bf16(acc[mi][ni], a_h[mi], b_h[ni]);
                    if (PROD == 3) {
                        mma_bf16(acc[mi][ni], a_h[mi], b_l[ni]);
                        mma_bf16(acc[mi][ni], a_l[mi], b_h[ni]);
                    }
                }
        }
    }

    // ---- epilogue ----
    const int N2 = N >> 1;
    #pragma unroll
    for (int mi = 0; mi < 2; mi++) {
        int r0 = m0 + wm * 32 + mi * 16 + l4;
        float mx0 = -CUDART_INF_F, mx1 = -CUDART_INF_F;
        #pragma unroll
        for (int ni = 0; ni < NI; ni++) {
            int c0 = n0 + wn * (BN / 2) + ni * 8 + 2 * lk;
            if (c0 < N) {
                float v0 = alpha * acc[mi][ni][0], v1 = alpha * acc[mi][ni][1];
                float v2 = alpha * acc[mi][ni][2], v3 = alpha * acc[mi][ni][3];
                int pj = c0 >> 1;
                if (MODE == 1) {
                    if (r0 < M) {
                        uint32_t hi, lo;
                        split_pair(v0, v1, hi, lo);
                        Ch[sC * b + (size_t)r0 * N2 + pj] = hi;
                        Cl[sC * b + (size_t)r0 * N2 + pj] = lo;
                    }
                    if (r0 + 8 < M) {
                        uint32_t hi, lo;
                        split_pair(v2, v3, hi, lo);
                        Ch[sC * b + (size_t)(r0 + 8) * N2 + pj] = hi;
                        Cl[sC * b + (size_t)(r0 + 8) * N2 + pj] = lo;
                    }
                } else {   // MODE == 2: packed bf16 logits + row max of stored values
                    __nv_bfloat16 q0 = __float2bfloat16_rn(v0);
                    __nv_bfloat16 q1 = __float2bfloat16_rn(v1);
                    __nv_bfloat16 q2 = __float2bfloat16_rn(v2);
                    __nv_bfloat16 q3 = __float2bfloat16_rn(v3);
                    if (r0 < M)
                        Ch[sC * b + (size_t)r0 * N2 + pj] =
                            ((uint32_t)__bfloat16_as_ushort(q1) << 16) | __bfloat16_as_ushort(q0);
                    if (r0 + 8 < M)
                        Ch[sC * b + (size_t)(r0 + 8) * N2 + pj] =
                            ((uint32_t)__bfloat16_as_ushort(q3) << 16) | __bfloat16_as_ushort(q2);
                    mx0 = fmaxf(mx0, fmaxf(__bfloat162float(q0), __bfloat162float(q1)));
                    mx1 = fmaxf(mx1, fmaxf(__bfloat162float(q2), __bfloat162float(q3)));
                }
            }
        }
        if (MODE == 2) {
            #pragma unroll
            for (int o = 1; o <= 2; o <<= 1) {
                mx0 = fmaxf(mx0, __shfl_xor_sync(0xffffffffu, mx0, o));
                mx1 = fmaxf(mx1, __shfl_xor_sync(0xffffffffu, mx1, o));
            }
            if (lk == 0 && mx0 > -CUDART_INF_F) {
                if (r0 < M)     atomicMax(&Mx[(size_t)b * M + r0], enc_f(mx0));
                if (r0 + 8 < M) atomicMax(&Mx[(size_t)b * M + r0 + 8], enc_f(mx1));
            }
        }
    }
}

// ---------------------------------------------------------------------------
// Sparse softmax-gather with exact recompute of candidate logits.
// Candidates: stored-bf16 logit > max_b - (THR_LN + SLACK). Exact logits
// recomputed as scale * (Yh+Yl) . H in fp32 (one warp per candidate).
// Deterministic: ballot-ordered compaction, fixed-order reductions.
// ---------------------------------------------------------------------------
#define SEG 173          // ceil(1380/8) elements per warp
#define CAP 176          // >= SEG: per-warp list cannot overflow

__global__ void softmax_gather(const float* __restrict__ H,
                               float* __restrict__ out) {
    const int c = blockIdx.x, b = blockIdx.y;
    const size_t row = (size_t)b * CN + c;
    const uint32_t* Lr = g_Lb + row * T2;
    const int tid = threadIdx.x;
    const int lane = tid & 31, warp = tid >> 5;
    const float scale = 1.0f / sqrtf((float)XD * (float)HD);

    const float M = dec_f(g_Mx[row]);
    const float thr = M - (THR_LN + SLACK);

    __shared__ uint32_t sidx[8 * CAP];
    __shared__ int      cnt[8];
    __shared__ int      off[9];
    __shared__ uint32_t fidx[T_];
    __shared__ float    flog[T_];
    __shared__ float    fp[T_];
    __shared__ float    sM2, sInv;

    // 1) one-pass candidate scan over stored bf16 logits
    {
        int s0 = warp * SEG;
        int s1 = min(s0 + SEG, T_);
        int base = 0;
        for (int i0 = s0; i0 < s1; i0 += 32) {
            int i = i0 + lane;
            float l = -CUDART_INF_F;
            if (i < s1) {
                uint32_t u = Lr[i >> 1];
                l = (i & 1) ? bf_hi(u) : bf_lo(u);
            }
            bool k = l > thr;
            unsigned bal = __ballot_sync(0xffffffffu, k);
            int o = __popc(bal & ((1u << lane) - 1u));
            if (k) sidx[warp * CAP + base + o] = (uint32_t)i;
            base += __popc(bal);
        }
        if (lane == 0) cnt[warp] = base;
    }
    __syncthreads();

    if (tid == 0) {
        int t = 0;
        #pragma unroll
        for (int w = 0; w < 8; w++) { off[w] = t; t += cnt[w]; }
        off[8] = t;
    }
    __syncthreads();
    {
        int n = cnt[warp], o = off[warp];
        for (int j = lane; j < n; j += 32)
            fidx[o + j] = sidx[warp * CAP + j];
    }
    __syncthreads();

    const int n = off[8];

    // 2) exact logits for candidates: one warp per candidate
    {
        const uint32_t* yh = g_Yh + row * HP2;
        const uint32_t* yl = g_Yl + row * HP2;
        for (int j = warp; j < n; j += 8) {
            const float* Hu = H + ((size_t)b * T_ + fidx[j]) * HD;
            float s = 0.f;
            for (int d = lane; d < HD; d += 32) {
                uint32_t uh = yh[d >> 1], ul = yl[d >> 1];
                float y = ((d & 1) ? bf_hi(uh) : bf_lo(uh))
                        + ((d & 1) ? bf_hi(ul) : bf_lo(ul));
                s += y * Hu[d];
            }
            #pragma unroll
            for (int o = 16; o > 0; o >>= 1)
                s += __shfl_xor_sync(0xffffffffu, s, o);
            if (lane == 0) flog[j] = s * scale;
        }
    }
    __syncthreads();

    // 3) exact softmax over candidates (thread 0, fixed order)
    if (tid == 0) {
        float M2 = -CUDART_INF_F;
        for (int j = 0; j < n; j++) M2 = fmaxf(M2, flog[j]);
        float S = 0.f;
        for (int j = 0; j < n; j++) S += __expf(flog[j] - M2);
        sM2 = M2;
        sInv = __frcp_rn(S);
    }
    __syncthreads();
    {
        float M2 = sM2, inv = sInv;
        for (int j = tid; j < n; j += 256)
            fp[j] = __expf(flog[j] - M2) * inv;
    }
    __syncthreads();

    // 4) gather output row (fixed order)
    const float* Hb = H + (size_t)b * T_ * HD;
    float* Orow = out + row * HD;
    for (int j = tid; j < HD; j += 256) {
        float a = 0.f;
        for (int k = 0; k < n; k++)
            a += fp[k] * Hb[(size_t)fidx[k] * HD + j];
        Orow[j] = a;
    }
}

// ---------------------------------------------------------------------------

static inline int cdiv(int a, int b) { return (a + b - 1) / b; }

extern "C" void kernel_launch(void* const* d_in, const int* in_sizes, int n_in,
                              void* d_out, int out_size) {
    const float* X  = (const float*)d_in[0];  // [B,T,XD]
    const float* H  = (const float*)d_in[1];  // [B,T,HD]
    const float* W1 = (const float*)d_in[2];  // [XD,HD]
    const float* W2 = (const float*)d_in[3];  // [CN,T]
    float* out = (float*)d_out;               // [B,CN,HD]

    uint32_t *W2h, *W2l, *Xth, *Xtl, *W1th, *W1tl, *Hh;
    uint32_t *Zh, *Zl, *Yh, *Yl, *Mx, *Lb;
    cudaGetSymbolAddress((void**)&W2h, g_W2h);  cudaGetSymbolAddress((void**)&W2l, g_W2l);
    cudaGetSymbolAddress((void**)&Xth, g_Xth);  cudaGetSymbolAddress((void**)&Xtl, g_Xtl);
    cudaGetSymbolAddress((void**)&W1th, g_W1th); cudaGetSymbolAddress((void**)&W1tl, g_W1tl);
    cudaGetSymbolAddress((void**)&Hh, g_Hh);
    cudaGetSymbolAddress((void**)&Zh, g_Zh);    cudaGetSymbolAddress((void**)&Zl, g_Zl);
    cudaGetSymbolAddress((void**)&Yh, g_Yh);    cudaGetSymbolAddress((void**)&Yl, g_Yl);
    cudaGetSymbolAddress((void**)&Mx, g_Mx);
    cudaGetSymbolAddress((void**)&Lb, g_Lb);

    const float scale = 1.0f / sqrtf((float)XD * (float)HD);

    constexpr int SMEM3 = 4 * (4096 + 96 * 32) * 4;   // 114688 B (split GEMM)
    constexpr int SMEM1 = 4 * (2048 + 96 * 16) * 4;   // 57344 B  (single-product GEMM)

    static bool attr_done = false;
    if (!attr_done) {
        cudaFuncSetAttribute(gemm_bf16s<96, 1, 3>,
            cudaFuncAttributeMaxDynamicSharedMemorySize, SMEM3);
        cudaFuncSetAttribute(gemm_bf16s<96, 2, 1>,
            cudaFuncAttributeMaxDynamicSharedMemorySize, SMEM1);
        attr_done = true;
    }

    // ---- prepass ----
    init_max<<<cdiv(B_ * CN, 256), 256>>>();
    {
        size_t tot = (size_t)CN * TP2;
        split_pack<<<(int)cdiv((int)tot, 256), 256>>>(W2, W2h, W2l, CN, T_, TP2);
    }
    {
        size_t tot = (size_t)B_ * T_ * HP2;
        pack_hi<<<(int)((tot + 255) / 256), 256>>>(H, Hh, B_ * T_, HD, HP2);
    }
    split_transpose<<<dim3(TP / 32, cdiv(XD, 32), B_), dim3(32, 8)>>>(
        X, (size_t)T_ * XD, Xth, Xtl, (size_t)XD * TP2, T_, XD, TP2);
    split_transpose<<<dim3(XD / 32, cdiv(HD, 32), 1), dim3(32, 8)>>>(
        W1, 0, W1th, W1tl, 0, XD, HD, XP2);

    // 1) Z[b] = W2 @ X[b]    (3-product split, split output)
    gemm_bf16s<96, 1, 3><<<dim3(cdiv(CN, 128), cdiv(XD, 96), B_), 256, SMEM3>>>(
        W2h, W2l, 0, Xth, Xtl, (size_t)XD * TP2,
        Zh, Zl, nullptr, (size_t)CN * XP2, CN, XD, TP, 1.0f);

    // 2) Y[b] = Z[b] @ W1    (3-product split, split output)
    gemm_bf16s<96, 1, 3><<<dim3(cdiv(CN, 128), cdiv(HD, 96), B_), 256, SMEM3>>>(
        Zh, Zl, (size_t)CN * XP2, W1th, W1tl, 0,
        Yh, Yl, nullptr, (size_t)CN * HP2, CN, HD, XD, 1.0f);

    // 3) Lb[b] = bf16(scale * Y[b] @ H[b]^T)  (single product, bf16 out + max)
    gemm_bf16s<96, 2, 1><<<dim3(cdiv(CN, 128), cdiv(T_, 96), B_), 256, SMEM1>>>(
        Yh, Yh, (size_t)CN * HP2, Hh, Hh, (size_t)T_ * HP2,
        Lb, nullptr, Mx, (size_t)CN * T2, CN, T_, HD, scale);

    // 4+5) candidate scan + exact recompute + gather -> out
    softmax_gather<<<dim3(CN, B_), 256>>>(H, out);
}